// round 13
// baseline (speedup 1.0000x reference)
#include <cuda_runtime.h>
#include <cuda_bf16.h>
#include <mma.h>
#include <math.h>
#include <stdint.h>

using namespace nvcuda;

#define T_STEPS 128
#define NB      256
#define E_DIM   512
#define A_DIM   8
#define H_DIM   512
#define G3      1536
#define TN      (T_STEPS * NB)
#define K_IN    (E_DIM + A_DIM)
#define K_PAD   544               // 512 (x) + 8 (ma) + 24 zero pad

// ---- scratch (device globals; no dynamic allocation allowed) ----
__device__ float g_GI[(size_t)TN * G3];   // input-side gates for gru (192 MiB)
__device__ float g_MA[TN * A_DIM];        // masked prev action
__device__ unsigned g_bar;                // global barrier counter

// pre-split bf16 operands
__device__ __nv_bfloat16 g_X2hi[(size_t)TN * K_PAD], g_X2lo[(size_t)TN * K_PAD]; // padded [x|ma|0]
__device__ __nv_bfloat16 g_W2hi[G3 * K_PAD],  g_W2lo[G3 * K_PAD];                // padded w_ih
__device__ __nv_bfloat16 g_Whh_hi[G3 * H_DIM], g_Whh_lo[G3 * H_DIM];
__device__ __nv_bfloat16 g_Whp_hi[G3 * H_DIM], g_Whp_lo[G3 * H_DIM];

__device__ __forceinline__ float sigmoidf_(float x) { return 1.0f / (1.0f + expf(-x)); }

__device__ __forceinline__ void split_bf16(float v, __nv_bfloat16& hi, __nv_bfloat16& lo) {
    hi = __float2bfloat16(v);
    lo = __float2bfloat16(v - __bfloat162float(hi));
}

__device__ __forceinline__ void store_split16(__nv_bfloat16* hiDst, __nv_bfloat16* loDst,
                                              const float av[16]) {
    __nv_bfloat162 hp[8], lp[8];
#pragma unroll
    for (int u = 0; u < 8; u++) {
        __nv_bfloat16 h0, l0, h1, l1;
        split_bf16(av[2 * u],     h0, l0);
        split_bf16(av[2 * u + 1], h1, l1);
        hp[u] = __halves2bfloat162(h0, h1);
        lp[u] = __halves2bfloat162(l0, l1);
    }
    *(uint4*)(hiDst)     = *(const uint4*)&hp[0];
    *(uint4*)(hiDst + 8) = *(const uint4*)&hp[4];
    *(uint4*)(loDst)     = *(const uint4*)&lp[0];
    *(uint4*)(loDst + 8) = *(const uint4*)&lp[4];
}

__device__ __forceinline__ void split_pack8(const float v[8], uint4& hv, uint4& lv) {
    __nv_bfloat162 hp[4], lp[4];
#pragma unroll
    for (int u = 0; u < 4; u++) {
        __nv_bfloat16 h0, l0, h1, l1;
        split_bf16(v[2 * u], h0, l0);
        split_bf16(v[2 * u + 1], h1, l1);
        hp[u] = __halves2bfloat162(h0, h1);
        lp[u] = __halves2bfloat162(l0, l1);
    }
    hv = *(const uint4*)&hp[0];
    lv = *(const uint4*)&lp[0];
}

// ---------------------------------------------------------------------------
// Prep kernels
// ---------------------------------------------------------------------------
__global__ void ma_kernel(const float* __restrict__ pa, const float* __restrict__ masks) {
    int i = blockIdx.x * blockDim.x + threadIdx.x;
    if (i < TN * A_DIM) g_MA[i] = pa[i] * masks[i >> 3];
}

__global__ void bar_reset_kernel() { g_bar = 0u; }

// padded X2 = [x | ma | 0] split to bf16 hi/lo
__global__ void x2_prep_kernel(const float* __restrict__ x) {
    size_t i8 = (size_t)(blockIdx.x * 256 + threadIdx.x) * 8;
    if (i8 >= (size_t)TN * K_PAD) return;
    int m = (int)(i8 / K_PAD);
    int k = (int)(i8 % K_PAD);
    float v[8];
    if (k < E_DIM) {
        float4 a = *(const float4*)(x + (size_t)m * E_DIM + k);
        float4 b = *(const float4*)(x + (size_t)m * E_DIM + k + 4);
        v[0]=a.x; v[1]=a.y; v[2]=a.z; v[3]=a.w; v[4]=b.x; v[5]=b.y; v[6]=b.z; v[7]=b.w;
    } else if (k == E_DIM) {
        float4 a = *(const float4*)&g_MA[(size_t)m * A_DIM];
        float4 b = *(const float4*)&g_MA[(size_t)m * A_DIM + 4];
        v[0]=a.x; v[1]=a.y; v[2]=a.z; v[3]=a.w; v[4]=b.x; v[5]=b.y; v[6]=b.z; v[7]=b.w;
    } else {
#pragma unroll
        for (int u = 0; u < 8; u++) v[u] = 0.0f;
    }
    uint4 hv, lv;
    split_pack8(v, hv, lv);
    *(uint4*)&g_X2hi[i8] = hv;
    *(uint4*)&g_X2lo[i8] = lv;
}

// padded w_ih split to bf16 hi/lo
__global__ void w2_prep_kernel(const float* __restrict__ w_ih) {
    int i8 = (blockIdx.x * 256 + threadIdx.x) * 8;
    if (i8 >= G3 * K_PAD) return;
    int j = i8 / K_PAD;
    int k = i8 % K_PAD;
    float v[8];
    if (k < K_IN) {
        float4 a = *(const float4*)(w_ih + (size_t)j * K_IN + k);
        float4 b = *(const float4*)(w_ih + (size_t)j * K_IN + k + 4);
        v[0]=a.x; v[1]=a.y; v[2]=a.z; v[3]=a.w; v[4]=b.x; v[5]=b.y; v[6]=b.z; v[7]=b.w;
    } else {
#pragma unroll
        for (int u = 0; u < 8; u++) v[u] = 0.0f;
    }
    uint4 hv, lv;
    split_pack8(v, hv, lv);
    *(uint4*)&g_W2hi[i8] = hv;
    *(uint4*)&g_W2lo[i8] = lv;
}

// hidden weights split (w_hh, w_hh_p)
__global__ void split2_kernel(const float* __restrict__ w_hh,
                              const float* __restrict__ w_hh_p) {
    int i8 = (blockIdx.x * 256 + threadIdx.x) * 8;
    if (i8 >= G3 * H_DIM) return;
    {
        float4 a = *(const float4*)(w_hh + i8);
        float4 b = *(const float4*)(w_hh + i8 + 4);
        float v[8] = {a.x,a.y,a.z,a.w,b.x,b.y,b.z,b.w};
        uint4 hv, lv; split_pack8(v, hv, lv);
        *(uint4*)&g_Whh_hi[i8] = hv;
        *(uint4*)&g_Whh_lo[i8] = lv;
    }
    {
        float4 a = *(const float4*)(w_hh_p + i8);
        float4 b = *(const float4*)(w_hh_p + i8 + 4);
        float v[8] = {a.x,a.y,a.z,a.w,b.x,b.y,b.z,b.w};
        uint4 hv, lv; split_pack8(v, hv, lv);
        *(uint4*)&g_Whp_hi[i8] = hv;
        *(uint4*)&g_Whp_lo[i8] = lv;
    }
}

// ---------------------------------------------------------------------------
// Input GEMM (bf16x3 wmma): g_GI = bias + X2 @ w_ih^T  (round-12 version)
// CTA: 256 rows x 48 gate-cols, K=544 in 17 chunks of 32, double-buffered,
// pure uint4 staging from pre-split buffers, 1 sync/chunk, 2 CTAs/SM.
// ---------------------------------------------------------------------------
#define SPI 40
#define AI_LO 10240
#define WI_HI 20480
#define WI_LO 22400
#define BUFI  24320
#define IG_SMEM (2 * BUFI * 2) // 97,280 bytes

__global__ void __launch_bounds__(256, 2)
input_gemm_kernel(const float* __restrict__ b_ih) {
    extern __shared__ __align__(16) float dynf[];
    __nv_bfloat16* ig = (__nv_bfloat16*)dynf;
    __shared__ float btile[16 * 48];

    const int j0 = blockIdx.x * 16;
    const int m0 = blockIdx.y * 256;
    const int tid = threadIdx.x;
    const int w = tid >> 5;

    const __nv_bfloat16* __restrict__ Xh = g_X2hi + (size_t)(m0 + tid) * K_PAD;
    const __nv_bfloat16* __restrict__ Xl = g_X2lo + (size_t)(m0 + tid) * K_PAD;
    const int sW = tid >> 2;
    const int seg8 = (tid & 3) * 8;
    const int wrow = (sW >> 4) * H_DIM + j0 + (sW & 15);
    const __nv_bfloat16* __restrict__ Wh = g_W2hi + (size_t)wrow * K_PAD;
    const __nv_bfloat16* __restrict__ Wl = g_W2lo + (size_t)wrow * K_PAD;

    for (int i = tid; i < 16 * 48; i += 256) {
        int c = i % 48;
        btile[i] = b_ih[(c >> 4) * H_DIM + j0 + (c & 15)];
    }
    __syncthreads();

    wmma::fragment<wmma::accumulator, 16, 16, 16, float> acc[2][3];
#pragma unroll
    for (int rt = 0; rt < 2; rt++)
#pragma unroll
        for (int g = 0; g < 3; g++)
            wmma::load_matrix_sync(acc[rt][g], &btile[g * 16], 48, wmma::mem_row_major);
    __syncthreads();

    // prefetch chunk 0
    uint4 ah[4], al[4], wh_, wl_;
#pragma unroll
    for (int qq = 0; qq < 4; qq++) {
        ah[qq] = *(const uint4*)(Xh + qq * 8);
        al[qq] = *(const uint4*)(Xl + qq * 8);
    }
    if (tid < 192) { wh_ = *(const uint4*)(Wh + seg8); wl_ = *(const uint4*)(Wl + seg8); }
#pragma unroll
    for (int qq = 0; qq < 4; qq++) {
        *(uint4*)&ig[tid * SPI + qq * 8]         = ah[qq];
        *(uint4*)&ig[AI_LO + tid * SPI + qq * 8] = al[qq];
    }
    if (tid < 192) {
        *(uint4*)&ig[WI_HI + sW * SPI + seg8] = wh_;
        *(uint4*)&ig[WI_LO + sW * SPI + seg8] = wl_;
    }
    __syncthreads();

    for (int ch = 0; ch <= 16; ch++) {
        const int cb = (ch & 1) * BUFI;
        const int nb = ((ch + 1) & 1) * BUFI;

        if (ch < 16) {
            const int kb = (ch + 1) * 32;
#pragma unroll
            for (int qq = 0; qq < 4; qq++) {
                ah[qq] = *(const uint4*)(Xh + kb + qq * 8);
                al[qq] = *(const uint4*)(Xl + kb + qq * 8);
            }
            if (tid < 192) {
                wh_ = *(const uint4*)(Wh + kb + seg8);
                wl_ = *(const uint4*)(Wl + kb + seg8);
            }
        }

#pragma unroll
        for (int k8 = 0; k8 < 2; k8++) {
            wmma::fragment<wmma::matrix_a, 16, 16, 16, __nv_bfloat16, wmma::row_major> a0h, a0l, a1h, a1l;
            wmma::load_matrix_sync(a0h, &ig[cb + (w * 32) * SPI + k8 * 16], SPI);
            wmma::load_matrix_sync(a0l, &ig[cb + AI_LO + (w * 32) * SPI + k8 * 16], SPI);
            wmma::load_matrix_sync(a1h, &ig[cb + (w * 32 + 16) * SPI + k8 * 16], SPI);
            wmma::load_matrix_sync(a1l, &ig[cb + AI_LO + (w * 32 + 16) * SPI + k8 * 16], SPI);
#pragma unroll
            for (int g = 0; g < 3; g++) {
                wmma::fragment<wmma::matrix_b, 16, 16, 16, __nv_bfloat16, wmma::col_major> bh, bl;
                wmma::load_matrix_sync(bh, &ig[cb + WI_HI + (g * 16) * SPI + k8 * 16], SPI);
                wmma::load_matrix_sync(bl, &ig[cb + WI_LO + (g * 16) * SPI + k8 * 16], SPI);
                wmma::mma_sync(acc[0][g], a0h, bh, acc[0][g]);
                wmma::mma_sync(acc[0][g], a0h, bl, acc[0][g]);
                wmma::mma_sync(acc[0][g], a0l, bh, acc[0][g]);
                wmma::mma_sync(acc[1][g], a1h, bh, acc[1][g]);
                wmma::mma_sync(acc[1][g], a1h, bl, acc[1][g]);
                wmma::mma_sync(acc[1][g], a1l, bh, acc[1][g]);
            }
        }

        if (ch < 16) {
#pragma unroll
            for (int qq = 0; qq < 4; qq++) {
                *(uint4*)&ig[nb + tid * SPI + qq * 8]         = ah[qq];
                *(uint4*)&ig[nb + AI_LO + tid * SPI + qq * 8] = al[qq];
            }
            if (tid < 192) {
                *(uint4*)&ig[nb + WI_HI + sW * SPI + seg8] = wh_;
                *(uint4*)&ig[nb + WI_LO + sW * SPI + seg8] = wl_;
            }
        }
        __syncthreads();
    }

#pragma unroll
    for (int rt = 0; rt < 2; rt++)
#pragma unroll
        for (int g = 0; g < 3; g++) {
            int row0 = m0 + w * 32 + rt * 16;
            int col0 = g * H_DIM + j0;
            wmma::store_matrix_sync(g_GI + (size_t)row0 * G3 + col0, acc[rt][g], G3,
                                    wmma::mem_row_major);
        }
}

// ---------------------------------------------------------------------------
// Persistent scan kernel — ROUND-11 EXACT (proven 26.6us/step). acc[3], no split.
// 128 CTAs x 512 threads, W resident in smem, global barrier between steps.
// ---------------------------------------------------------------------------
#define WPCH 520
#define SP2 40
#define WSP 56
#define W_LO_OFF 24960
#define AB_OFF   49920
#define ABUF     10240
#define SCAN_SMEM ((AB_OFF + 4 * ABUF) * 2)   // 181,760 bytes

__device__ __forceinline__ void load_a16_cg(const float* __restrict__ hrow,
                                            const float* __restrict__ grw,
                                            int kb, bool isp, float mr, float omr,
                                            float av[16]) {
    float4 h0 = __ldcg((const float4*)(hrow + kb));
    float4 h1 = __ldcg((const float4*)(hrow + kb + 4));
    float4 h2 = __ldcg((const float4*)(hrow + kb + 8));
    float4 h3 = __ldcg((const float4*)(hrow + kb + 12));
    av[0]=h0.x; av[1]=h0.y; av[2]=h0.z;  av[3]=h0.w;
    av[4]=h1.x; av[5]=h1.y; av[6]=h1.z;  av[7]=h1.w;
    av[8]=h2.x; av[9]=h2.y; av[10]=h2.z; av[11]=h2.w;
    av[12]=h3.x; av[13]=h3.y; av[14]=h3.z; av[15]=h3.w;
    if (isp) {
        float4 g0 = *(const float4*)(grw + kb);
        float4 g1 = *(const float4*)(grw + kb + 4);
        float4 g2 = *(const float4*)(grw + kb + 8);
        float4 g3 = *(const float4*)(grw + kb + 12);
        float gv[16] = {g0.x,g0.y,g0.z,g0.w, g1.x,g1.y,g1.z,g1.w,
                        g2.x,g2.y,g2.z,g2.w, g3.x,g3.y,g3.z,g3.w};
#pragma unroll
        for (int u = 0; u < 16; u++) av[u] = av[u] * mr + gv[u] * omr;
    } else {
#pragma unroll
        for (int u = 0; u < 16; u++) av[u] = av[u] * mr;
    }
}

__global__ void __launch_bounds__(512)
scan_kernel(const float* __restrict__ hxs, const float* __restrict__ hys,
            const float* __restrict__ gru_init, const float* __restrict__ masks,
            const float* __restrict__ b_hh, const float* __restrict__ b_hh_p,
            const float* __restrict__ w_ih_p, const float* __restrict__ b_ih_p,
            float* __restrict__ outs, float* __restrict__ outs_p) {
    extern __shared__ __align__(16) float dyn[];
    __shared__ float wp[48 * 8];
    __shared__ float bgs[48];
    __shared__ float bip[48];

    __nv_bfloat16* smb = (__nv_bfloat16*)dyn;
    float* Cf = dyn + W_LO_OFF;

    const int cta = blockIdx.x;
    const bool isp = (cta >= 64);
    const int q = cta & 63;
    const int j0 = (q >> 1) * 16;
    const int mbase = (q & 1) * 128;

    const __nv_bfloat16* __restrict__ WhiG = isp ? g_Whp_hi : g_Whh_hi;
    const __nv_bfloat16* __restrict__ WloG = isp ? g_Whp_lo : g_Whh_lo;
    const float* __restrict__ bh = isp ? b_hh_p : b_hh;

    const int tid = threadIdx.x;
    const int grp  = tid >> 8;
    const int gtid = tid & 255;
    const int wg   = (tid >> 5) & 7;
    const int kg0  = grp * 256;

    const int lr  = gtid >> 1;
    const int kh2 = (gtid & 1) * 16;
    const int grow = mbase + lr;
    const int er  = tid >> 2;
    const int cq  = (tid & 3) * 4;
    const int egrow = mbase + er;

    // ---- one-time setup: stage W resident, biases, wp ----
    for (int i = tid; i < 48 * 64; i += 512) {
        const int r = i >> 6, s8 = (i & 63) * 8;
        const int wr = (r >> 4) * H_DIM + j0 + (r & 15);
        *(uint4*)&smb[r * WPCH + s8]            = *(const uint4*)&WhiG[(size_t)wr * H_DIM + s8];
        *(uint4*)&smb[W_LO_OFF + r * WPCH + s8] = *(const uint4*)&WloG[(size_t)wr * H_DIM + s8];
    }
    if (tid < 48) {
        const int gidx = (tid >> 4) * H_DIM + j0 + (tid & 15);
        bgs[tid] = bh[gidx];
        bip[tid] = b_ih_p[gidx];
    }
    if (tid < 96) {
        const int s = tid >> 1, hf = (tid & 1) * 4;
        const int gidx = (s >> 4) * H_DIM + j0 + (s & 15);
        *(float4*)&wp[s * 8 + hf] = *(const float4*)&w_ih_p[(size_t)gidx * A_DIM + hf];
    }
    __syncthreads();

    for (int t = 0; t < T_STEPS; t++) {
        const float* __restrict__ hxp = t ? outs   + (size_t)(t - 1) * NB * H_DIM : hxs;
        const float* __restrict__ hyp = t ? outs_p + (size_t)(t - 1) * NB * H_DIM : hys;
        const float* __restrict__ hp = isp ? hyp : hxp;
        float* __restrict__ hout = (isp ? outs_p : outs) + (size_t)t * NB * H_DIM;
        const float* __restrict__ masks_t = masks + t * NB;
        const float* __restrict__ g_t = gru_init + (size_t)t * NB * H_DIM;

        const float mr = masks_t[grow];
        const float omr = 1.0f - mr;
        const float* __restrict__ hrow = hp  + (size_t)grow * H_DIM + kg0;
        const float* __restrict__ grw  = g_t + (size_t)grow * H_DIM + kg0;

        // ---- epilogue prefetch ----
        const float emr = masks_t[egrow];
        float4 hv4 = __ldcg((const float4*)(hp + (size_t)egrow * H_DIM + j0 + cq));
        float4 gg4, gi_r4, gi_z4, gi_n4;
        float ma8[8];
        if (isp) {
            gg4 = *(const float4*)(g_t + (size_t)egrow * H_DIM + j0 + cq);
            float4 m0 = *(const float4*)&g_MA[((size_t)t * NB + egrow) * A_DIM];
            float4 m1 = *(const float4*)&g_MA[((size_t)t * NB + egrow) * A_DIM + 4];
            ma8[0]=m0.x; ma8[1]=m0.y; ma8[2]=m0.z; ma8[3]=m0.w;
            ma8[4]=m1.x; ma8[5]=m1.y; ma8[6]=m1.z; ma8[7]=m1.w;
        } else {
            const float* __restrict__ gi = g_GI + ((size_t)t * NB + egrow) * G3 + j0;
            gi_r4 = *(const float4*)(gi + cq);
            gi_z4 = *(const float4*)(gi + 512 + cq);
            gi_n4 = *(const float4*)(gi + 1024 + cq);
        }

        wmma::fragment<wmma::accumulator, 16, 16, 16, float> acc[3];
#pragma unroll
        for (int g = 0; g < 3; g++) wmma::fill_fragment(acc[g], 0.0f);

        // stage chunk 0 into this group's buffer 0
        {
            float av[16];
            load_a16_cg(hrow, grw, kh2, isp, mr, omr, av);
            const int b0 = AB_OFF + grp * 2 * ABUF;
            store_split16(smb + b0 + lr * SP2 + kh2,
                          smb + b0 + 5120 + lr * SP2 + kh2, av);
        }
        __syncthreads();

        for (int ch = 0; ch < 8; ch++) {
            const int cb = AB_OFF + (grp * 2 + (ch & 1)) * ABUF;
            const int nb = AB_OFF + (grp * 2 + ((ch + 1) & 1)) * ABUF;

            float av[16];
            if (ch < 7) load_a16_cg(hrow, grw, (ch + 1) * 32 + kh2, isp, mr, omr, av);

#pragma unroll
            for (int k8 = 0; k8 < 2; k8++) {
                const int kg = kg0 + ch * 32 + k8 * 16;
                wmma::fragment<wmma::matrix_a, 16, 16, 16, __nv_bfloat16, wmma::row_major> ahiF, aloF;
                wmma::load_matrix_sync(ahiF, &smb[cb + (wg * 16) * SP2 + k8 * 16], SP2);
                wmma::load_matrix_sync(aloF, &smb[cb + 5120 + (wg * 16) * SP2 + k8 * 16], SP2);
#pragma unroll
                for (int g = 0; g < 3; g++) {
                    wmma::fragment<wmma::matrix_b, 16, 16, 16, __nv_bfloat16, wmma::col_major> bhiF, bloF;
                    wmma::load_matrix_sync(bhiF, &smb[(g * 16) * WPCH + kg], WPCH);
                    wmma::load_matrix_sync(bloF, &smb[W_LO_OFF + (g * 16) * WPCH + kg], WPCH);
                    wmma::mma_sync(acc[g], ahiF, bhiF, acc[g]);
                    wmma::mma_sync(acc[g], ahiF, bloF, acc[g]);
                    wmma::mma_sync(acc[g], aloF, bhiF, acc[g]);
                }
            }

            if (ch < 7) {
                store_split16(smb + nb + lr * SP2 + kh2,
                              smb + nb + 5120 + lr * SP2 + kh2, av);
            }
            __syncthreads();
        }

        // ---- partial C tiles to smem (overlay A region) ----
        float* Csh = Cf + grp * 128 * WSP;
#pragma unroll
        for (int g = 0; g < 3; g++)
            wmma::store_matrix_sync(&Csh[(wg * 16) * WSP + g * 16], acc[g], WSP,
                                    wmma::mem_row_major);
        __syncthreads();

        // ---- fused gate epilogue: row er, 4 cols at cq ----
        const float* __restrict__ C0 = Cf + er * WSP;
        const float* __restrict__ C1 = Cf + 128 * WSP + er * WSP;
        float cr[4], cz[4], cn[4];
#pragma unroll
        for (int u = 0; u < 4; u++) {
            cr[u] = C0[cq + u]      + C1[cq + u];
            cz[u] = C0[16 + cq + u] + C1[16 + cq + u];
            cn[u] = C0[32 + cq + u] + C1[32 + cq + u];
        }

        float gr_[4], gz_[4], gn_[4];
        if (!isp) {
            *(float4*)&gr_[0] = gi_r4;
            *(float4*)&gz_[0] = gi_z4;
            *(float4*)&gn_[0] = gi_n4;
        } else {
#pragma unroll
            for (int u = 0; u < 4; u++) {
                const int jc = cq + u;
                float ir = bip[jc], iz = bip[16 + jc], in_ = bip[32 + jc];
#pragma unroll
                for (int a = 0; a < 8; a++) {
                    ir  += ma8[a] * wp[jc * 8 + a];
                    iz  += ma8[a] * wp[(16 + jc) * 8 + a];
                    in_ += ma8[a] * wp[(32 + jc) * 8 + a];
                }
                gr_[u] = ir; gz_[u] = iz; gn_[u] = in_;
            }
        }

        float hv[4], hing[4];
        *(float4*)&hv[0] = hv4;
        if (isp) {
            float gg[4];
            *(float4*)&gg[0] = gg4;
#pragma unroll
            for (int u = 0; u < 4; u++) hing[u] = hv[u] * emr + gg[u] * (1.0f - emr);
        } else {
#pragma unroll
            for (int u = 0; u < 4; u++) hing[u] = hv[u] * emr;
        }

        float outv[4];
#pragma unroll
        for (int u = 0; u < 4; u++) {
            const int jc = cq + u;
            float r  = sigmoidf_(gr_[u] + cr[u] + bgs[jc]);
            float z  = sigmoidf_(gz_[u] + cz[u] + bgs[16 + jc]);
            float nn = tanhf(gn_[u] + r * (cn[u] + bgs[32 + jc]));
            outv[u] = (1.0f - z) * nn + z * hing[u];
        }
        *(float4*)(hout + (size_t)egrow * H_DIM + j0 + cq) = *(const float4*)&outv[0];

        // ---- global barrier between steps ----
        __syncthreads();
        if (tid == 0) {
            __threadfence();
            atomicAdd(&g_bar, 1u);
            const unsigned tgt = (unsigned)(t + 1) * 128u;
            unsigned v;
            do {
                asm volatile("ld.acquire.gpu.u32 %0, [%1];" : "=r"(v) : "l"(&g_bar));
                if (v < tgt) __nanosleep(32);
            } while (v < tgt);
        }
        __syncthreads();
    }
}

// ---------------------------------------------------------------------------
// Launch
// ---------------------------------------------------------------------------
extern "C" void kernel_launch(void* const* d_in, const int* in_sizes, int n_in,
                              void* d_out, int out_size) {
    const float* x        = (const float*)d_in[0];
    const float* hxs      = (const float*)d_in[1];
    const float* hys      = (const float*)d_in[2];
    const float* gru_init = (const float*)d_in[3];
    const float* masks    = (const float*)d_in[4];
    const float* pa       = (const float*)d_in[5];
    const float* w_ih     = (const float*)d_in[6];
    const float* w_hh     = (const float*)d_in[7];
    const float* b_ih     = (const float*)d_in[8];
    const float* b_hh     = (const float*)d_in[9];
    const float* w_ih_p   = (const float*)d_in[10];
    const float* w_hh_p   = (const float*)d_in[11];
    const float* b_ih_p   = (const float*)d_in[12];
    const float* b_hh_p   = (const float*)d_in[13];

    float* out      = (float*)d_out;
    float* outs     = out;                                   // (TN, H)
    float* hxs_out  = outs + (size_t)TN * H_DIM;             // (N, H)
    float* outs_p   = hxs_out + (size_t)NB * H_DIM;          // (TN, H)
    float* hys_out  = outs_p + (size_t)TN * H_DIM;           // (N, H)

    cudaFuncSetAttribute(scan_kernel, cudaFuncAttributeMaxDynamicSharedMemorySize,
                         SCAN_SMEM);
    cudaFuncSetAttribute(input_gemm_kernel, cudaFuncAttributeMaxDynamicSharedMemorySize,
                         IG_SMEM);

    // 1) prep
    ma_kernel<<<(TN * A_DIM + 255) / 256, 256>>>(pa, masks);
    x2_prep_kernel<<<(int)(((size_t)TN * K_PAD / 8 + 255) / 256), 256>>>(x);
    w2_prep_kernel<<<(G3 * K_PAD / 8 + 255) / 256, 256>>>(w_ih);
    split2_kernel<<<(G3 * H_DIM / 8 + 255) / 256, 256>>>(w_hh, w_hh_p);
    bar_reset_kernel<<<1, 1>>>();

    // 2) input GEMM: g_GI complete
    input_gemm_kernel<<<dim3(G3 / 48, TN / 256), 256, IG_SMEM>>>(b_ih);

    // 3) persistent scan: all 128 steps in one launch
    scan_kernel<<<128, 512, SCAN_SMEM>>>(hxs, hys, gru_init, masks,
                                         b_hh, b_hh_p, w_ih_p, b_ih_p,
                                         outs, outs_p);

    // 4) final hidden states = last timestep outputs
    cudaMemcpyAsync(hxs_out, outs   + (size_t)(T_STEPS - 1) * NB * H_DIM,
                    (size_t)NB * H_DIM * sizeof(float), cudaMemcpyDeviceToDevice);
    cudaMemcpyAsync(hys_out, outs_p + (size_t)(T_STEPS - 1) * NB * H_DIM,
                    (size_t)NB * H_DIM * sizeof(float), cudaMemcpyDeviceToDevice);
}

// round 14
// speedup vs baseline: 1.0382x; 1.0382x over previous
#include <cuda_runtime.h>
#include <cuda_bf16.h>
#include <mma.h>
#include <math.h>
#include <stdint.h>

using namespace nvcuda;

#define T_STEPS 128
#define NB      256
#define E_DIM   512
#define A_DIM   8
#define H_DIM   512
#define G3      1536
#define TN      (T_STEPS * NB)
#define K_IN    (E_DIM + A_DIM)

// ---- scratch (device globals; no dynamic allocation allowed) ----
__device__ float g_GI[(size_t)TN * G3];   // input-side gates for gru (192 MiB)
__device__ float g_MA[TN * A_DIM];        // masked prev action
__device__ unsigned g_bar;                // global barrier counter

// pre-split bf16 weights (hi/lo)
__device__ __nv_bfloat16 g_Wih_hi[G3 * K_IN],  g_Wih_lo[G3 * K_IN];
__device__ __nv_bfloat16 g_Whh_hi[G3 * H_DIM], g_Whh_lo[G3 * H_DIM];
__device__ __nv_bfloat16 g_Whp_hi[G3 * H_DIM], g_Whp_lo[G3 * H_DIM];

__device__ __forceinline__ float sigmoidf_(float x) { return 1.0f / (1.0f + expf(-x)); }

__device__ __forceinline__ void split_bf16(float v, __nv_bfloat16& hi, __nv_bfloat16& lo) {
    hi = __float2bfloat16(v);
    lo = __float2bfloat16(v - __bfloat162float(hi));
}

__device__ __forceinline__ void store_split16(__nv_bfloat16* hiDst, __nv_bfloat16* loDst,
                                              const float av[16]) {
    __nv_bfloat162 hp[8], lp[8];
#pragma unroll
    for (int u = 0; u < 8; u++) {
        __nv_bfloat16 h0, l0, h1, l1;
        split_bf16(av[2 * u],     h0, l0);
        split_bf16(av[2 * u + 1], h1, l1);
        hp[u] = __halves2bfloat162(h0, h1);
        lp[u] = __halves2bfloat162(l0, l1);
    }
    *(uint4*)(hiDst)     = *(const uint4*)&hp[0];
    *(uint4*)(hiDst + 8) = *(const uint4*)&hp[4];
    *(uint4*)(loDst)     = *(const uint4*)&lp[0];
    *(uint4*)(loDst + 8) = *(const uint4*)&lp[4];
}

// ---------------------------------------------------------------------------
// Prep kernels (round-11 exact)
// ---------------------------------------------------------------------------
__global__ void ma_kernel(const float* __restrict__ pa, const float* __restrict__ masks) {
    int i = blockIdx.x * blockDim.x + threadIdx.x;
    if (i < TN * A_DIM) g_MA[i] = pa[i] * masks[i >> 3];
}

__global__ void bar_reset_kernel() { g_bar = 0u; }

__global__ void split3_kernel(const float* __restrict__ w_ih,
                              const float* __restrict__ w_hh,
                              const float* __restrict__ w_hh_p) {
    int i8 = (blockIdx.x * blockDim.x + threadIdx.x) * 8;
    if (i8 < G3 * K_IN) {
        float4 v0 = *(const float4*)(w_ih + i8);
        float4 v1 = *(const float4*)(w_ih + i8 + 4);
        float v[8] = {v0.x, v0.y, v0.z, v0.w, v1.x, v1.y, v1.z, v1.w};
        __nv_bfloat162 hp[4], lp[4];
#pragma unroll
        for (int u = 0; u < 4; u++) {
            __nv_bfloat16 h0, l0, h1, l1;
            split_bf16(v[2 * u], h0, l0);
            split_bf16(v[2 * u + 1], h1, l1);
            hp[u] = __halves2bfloat162(h0, h1);
            lp[u] = __halves2bfloat162(l0, l1);
        }
        *(uint4*)&g_Wih_hi[i8] = *(const uint4*)&hp[0];
        *(uint4*)&g_Wih_lo[i8] = *(const uint4*)&lp[0];
    }
    if (i8 < G3 * H_DIM) {
        {
            float4 v0 = *(const float4*)(w_hh + i8);
            float4 v1 = *(const float4*)(w_hh + i8 + 4);
            float v[8] = {v0.x, v0.y, v0.z, v0.w, v1.x, v1.y, v1.z, v1.w};
            __nv_bfloat162 hp[4], lp[4];
#pragma unroll
            for (int u = 0; u < 4; u++) {
                __nv_bfloat16 h0, l0, h1, l1;
                split_bf16(v[2 * u], h0, l0);
                split_bf16(v[2 * u + 1], h1, l1);
                hp[u] = __halves2bfloat162(h0, h1);
                lp[u] = __halves2bfloat162(l0, l1);
            }
            *(uint4*)&g_Whh_hi[i8] = *(const uint4*)&hp[0];
            *(uint4*)&g_Whh_lo[i8] = *(const uint4*)&lp[0];
        }
        {
            float4 v0 = *(const float4*)(w_hh_p + i8);
            float4 v1 = *(const float4*)(w_hh_p + i8 + 4);
            float v[8] = {v0.x, v0.y, v0.z, v0.w, v1.x, v1.y, v1.z, v1.w};
            __nv_bfloat162 hp[4], lp[4];
#pragma unroll
            for (int u = 0; u < 4; u++) {
                __nv_bfloat16 h0, l0, h1, l1;
                split_bf16(v[2 * u], h0, l0);
                split_bf16(v[2 * u + 1], h1, l1);
                hp[u] = __halves2bfloat162(h0, h1);
                lp[u] = __halves2bfloat162(l0, l1);
            }
            *(uint4*)&g_Whp_hi[i8] = *(const uint4*)&hp[0];
            *(uint4*)&g_Whp_lo[i8] = *(const uint4*)&lp[0];
        }
    }
}

// ---------------------------------------------------------------------------
// Input GEMM (bf16x3 wmma, round-11 exact — proven 960us)
// CTA: 256 rows x 48 gate-cols, K=520 in 33 chunks of 16 (chunk 32 = MA tail).
// grid: (32, 128), 256 threads.
// ---------------------------------------------------------------------------
#define SP 24

__global__ void __launch_bounds__(256)
input_gemm_kernel(const float* __restrict__ X, const float* __restrict__ b_ih) {
    __shared__ __nv_bfloat16 Ahi[256 * SP], Alo[256 * SP];
    __shared__ __nv_bfloat16 Whi[48 * SP],  Wlo[48 * SP];
    __shared__ float btile[16 * 48];

    const int j0 = blockIdx.x * 16;
    const int m0 = blockIdx.y * 256;
    const int tid = threadIdx.x;
    const int w = tid >> 5;

    const int m = m0 + tid;
    const float* __restrict__ Xr = X + (size_t)m * E_DIM;
    const int sW = tid >> 2;
    const int segW = (tid & 3) * 4;
    const int wrow = (sW >> 4) * H_DIM + j0 + (sW & 15);

    for (int i = tid; i < 16 * 48; i += 256) {
        int c = i % 48;
        btile[i] = b_ih[(c >> 4) * H_DIM + j0 + (c & 15)];
    }
    __syncthreads();

    wmma::fragment<wmma::accumulator, 16, 16, 16, float> acc[2][3];
#pragma unroll
    for (int rt = 0; rt < 2; rt++)
#pragma unroll
        for (int g = 0; g < 3; g++)
            wmma::load_matrix_sync(acc[rt][g], &btile[g * 16], 48, wmma::mem_row_major);
    __syncthreads();

    for (int ch = 0; ch < 33; ch++) {
        float av[16];
        if (ch < 32) {
            const int kb = ch * 16;
            float4 a0 = *(const float4*)(Xr + kb);
            float4 a1 = *(const float4*)(Xr + kb + 4);
            float4 a2 = *(const float4*)(Xr + kb + 8);
            float4 a3 = *(const float4*)(Xr + kb + 12);
            av[0]=a0.x; av[1]=a0.y; av[2]=a0.z;  av[3]=a0.w;
            av[4]=a1.x; av[5]=a1.y; av[6]=a1.z;  av[7]=a1.w;
            av[8]=a2.x; av[9]=a2.y; av[10]=a2.z; av[11]=a2.w;
            av[12]=a3.x; av[13]=a3.y; av[14]=a3.z; av[15]=a3.w;
        } else {
            float4 m0v = *(const float4*)&g_MA[(size_t)m * A_DIM];
            float4 m1v = *(const float4*)&g_MA[(size_t)m * A_DIM + 4];
            av[0]=m0v.x; av[1]=m0v.y; av[2]=m0v.z; av[3]=m0v.w;
            av[4]=m1v.x; av[5]=m1v.y; av[6]=m1v.z; av[7]=m1v.w;
#pragma unroll
            for (int u = 8; u < 16; u++) av[u] = 0.0f;
        }
        store_split16(&Ahi[tid * SP], &Alo[tid * SP], av);

        if (tid < 192) {
            const bool pad = (ch == 32) && (segW >= 8);
            const size_t off = (size_t)wrow * K_IN + ch * 16 + segW;
            uint2 hv = pad ? make_uint2(0, 0) : *(const uint2*)(g_Wih_hi + off);
            uint2 lv = pad ? make_uint2(0, 0) : *(const uint2*)(g_Wih_lo + off);
            *(uint2*)&Whi[sW * SP + segW] = hv;
            *(uint2*)&Wlo[sW * SP + segW] = lv;
        }
        __syncthreads();

#pragma unroll
        for (int rt = 0; rt < 2; rt++) {
            wmma::fragment<wmma::matrix_a, 16, 16, 16, __nv_bfloat16, wmma::row_major> ahiF, aloF;
            wmma::load_matrix_sync(ahiF, &Ahi[(w * 32 + rt * 16) * SP], SP);
            wmma::load_matrix_sync(aloF, &Alo[(w * 32 + rt * 16) * SP], SP);
#pragma unroll
            for (int g = 0; g < 3; g++) {
                wmma::fragment<wmma::matrix_b, 16, 16, 16, __nv_bfloat16, wmma::col_major> bhiF, bloF;
                wmma::load_matrix_sync(bhiF, &Whi[(g * 16) * SP], SP);
                wmma::load_matrix_sync(bloF, &Wlo[(g * 16) * SP], SP);
                wmma::mma_sync(acc[rt][g], ahiF, bhiF, acc[rt][g]);
                wmma::mma_sync(acc[rt][g], ahiF, bloF, acc[rt][g]);
                wmma::mma_sync(acc[rt][g], aloF, bhiF, acc[rt][g]);
            }
        }
        __syncthreads();
    }

#pragma unroll
    for (int rt = 0; rt < 2; rt++)
#pragma unroll
        for (int g = 0; g < 3; g++) {
            int row0 = m0 + w * 32 + rt * 16;
            int col0 = g * H_DIM + j0;
            wmma::store_matrix_sync(g_GI + (size_t)row0 * G3 + col0, acc[rt][g], G3,
                                    wmma::mem_row_major);
        }
}

// ---------------------------------------------------------------------------
// Persistent scan kernel: round-11 base + k8-split accumulators (round-12's
// scan change, empirically -59us holding IG fixed).
// 128 CTAs x 512 threads, W resident in smem, global barrier between steps.
// ---------------------------------------------------------------------------
#define WPCH 520
#define SP2 40
#define WSP 56
#define W_LO_OFF 24960
#define AB_OFF   49920
#define ABUF     10240
#define SCAN_SMEM ((AB_OFF + 4 * ABUF) * 2)   // 181,760 bytes

__device__ __forceinline__ void load_a16_cg(const float* __restrict__ hrow,
                                            const float* __restrict__ grw,
                                            int kb, bool isp, float mr, float omr,
                                            float av[16]) {
    float4 h0 = __ldcg((const float4*)(hrow + kb));
    float4 h1 = __ldcg((const float4*)(hrow + kb + 4));
    float4 h2 = __ldcg((const float4*)(hrow + kb + 8));
    float4 h3 = __ldcg((const float4*)(hrow + kb + 12));
    av[0]=h0.x; av[1]=h0.y; av[2]=h0.z;  av[3]=h0.w;
    av[4]=h1.x; av[5]=h1.y; av[6]=h1.z;  av[7]=h1.w;
    av[8]=h2.x; av[9]=h2.y; av[10]=h2.z; av[11]=h2.w;
    av[12]=h3.x; av[13]=h3.y; av[14]=h3.z; av[15]=h3.w;
    if (isp) {
        float4 g0 = *(const float4*)(grw + kb);
        float4 g1 = *(const float4*)(grw + kb + 4);
        float4 g2 = *(const float4*)(grw + kb + 8);
        float4 g3 = *(const float4*)(grw + kb + 12);
        float gv[16] = {g0.x,g0.y,g0.z,g0.w, g1.x,g1.y,g1.z,g1.w,
                        g2.x,g2.y,g2.z,g2.w, g3.x,g3.y,g3.z,g3.w};
#pragma unroll
        for (int u = 0; u < 16; u++) av[u] = av[u] * mr + gv[u] * omr;
    } else {
#pragma unroll
        for (int u = 0; u < 16; u++) av[u] = av[u] * mr;
    }
}

__global__ void __launch_bounds__(512)
scan_kernel(const float* __restrict__ hxs, const float* __restrict__ hys,
            const float* __restrict__ gru_init, const float* __restrict__ masks,
            const float* __restrict__ b_hh, const float* __restrict__ b_hh_p,
            const float* __restrict__ w_ih_p, const float* __restrict__ b_ih_p,
            float* __restrict__ outs, float* __restrict__ outs_p) {
    extern __shared__ __align__(16) float dyn[];
    __shared__ float wp[48 * 8];
    __shared__ float bgs[48];
    __shared__ float bip[48];

    __nv_bfloat16* smb = (__nv_bfloat16*)dyn;
    float* Cf = dyn + W_LO_OFF;

    const int cta = blockIdx.x;
    const bool isp = (cta >= 64);
    const int q = cta & 63;
    const int j0 = (q >> 1) * 16;
    const int mbase = (q & 1) * 128;

    const __nv_bfloat16* __restrict__ WhiG = isp ? g_Whp_hi : g_Whh_hi;
    const __nv_bfloat16* __restrict__ WloG = isp ? g_Whp_lo : g_Whh_lo;
    const float* __restrict__ bh = isp ? b_hh_p : b_hh;

    const int tid = threadIdx.x;
    const int grp  = tid >> 8;
    const int gtid = tid & 255;
    const int wg   = (tid >> 5) & 7;
    const int kg0  = grp * 256;

    const int lr  = gtid >> 1;
    const int kh2 = (gtid & 1) * 16;
    const int grow = mbase + lr;
    const int er  = tid >> 2;
    const int cq  = (tid & 3) * 4;
    const int egrow = mbase + er;

    // ---- one-time setup: stage W resident, biases, wp ----
    for (int i = tid; i < 48 * 64; i += 512) {
        const int r = i >> 6, s8 = (i & 63) * 8;
        const int wr = (r >> 4) * H_DIM + j0 + (r & 15);
        *(uint4*)&smb[r * WPCH + s8]            = *(const uint4*)&WhiG[(size_t)wr * H_DIM + s8];
        *(uint4*)&smb[W_LO_OFF + r * WPCH + s8] = *(const uint4*)&WloG[(size_t)wr * H_DIM + s8];
    }
    if (tid < 48) {
        const int gidx = (tid >> 4) * H_DIM + j0 + (tid & 15);
        bgs[tid] = bh[gidx];
        bip[tid] = b_ih_p[gidx];
    }
    if (tid < 96) {
        const int s = tid >> 1, hf = (tid & 1) * 4;
        const int gidx = (s >> 4) * H_DIM + j0 + (s & 15);
        *(float4*)&wp[s * 8 + hf] = *(const float4*)&w_ih_p[(size_t)gidx * A_DIM + hf];
    }
    __syncthreads();

    for (int t = 0; t < T_STEPS; t++) {
        const float* __restrict__ hxp = t ? outs   + (size_t)(t - 1) * NB * H_DIM : hxs;
        const float* __restrict__ hyp = t ? outs_p + (size_t)(t - 1) * NB * H_DIM : hys;
        const float* __restrict__ hp = isp ? hyp : hxp;
        float* __restrict__ hout = (isp ? outs_p : outs) + (size_t)t * NB * H_DIM;
        const float* __restrict__ masks_t = masks + t * NB;
        const float* __restrict__ g_t = gru_init + (size_t)t * NB * H_DIM;

        const float mr = masks_t[grow];
        const float omr = 1.0f - mr;
        const float* __restrict__ hrow = hp  + (size_t)grow * H_DIM + kg0;
        const float* __restrict__ grw  = g_t + (size_t)grow * H_DIM + kg0;

        // ---- epilogue prefetch ----
        const float emr = masks_t[egrow];
        float4 hv4 = __ldcg((const float4*)(hp + (size_t)egrow * H_DIM + j0 + cq));
        float4 gg4, gi_r4, gi_z4, gi_n4;
        float ma8[8];
        if (isp) {
            gg4 = *(const float4*)(g_t + (size_t)egrow * H_DIM + j0 + cq);
            float4 m0 = *(const float4*)&g_MA[((size_t)t * NB + egrow) * A_DIM];
            float4 m1 = *(const float4*)&g_MA[((size_t)t * NB + egrow) * A_DIM + 4];
            ma8[0]=m0.x; ma8[1]=m0.y; ma8[2]=m0.z; ma8[3]=m0.w;
            ma8[4]=m1.x; ma8[5]=m1.y; ma8[6]=m1.z; ma8[7]=m1.w;
        } else {
            const float* __restrict__ gi = g_GI + ((size_t)t * NB + egrow) * G3 + j0;
            gi_r4 = *(const float4*)(gi + cq);
            gi_z4 = *(const float4*)(gi + 512 + cq);
            gi_n4 = *(const float4*)(gi + 1024 + cq);
        }

        wmma::fragment<wmma::accumulator, 16, 16, 16, float> acc[2][3];
#pragma unroll
        for (int k8 = 0; k8 < 2; k8++)
#pragma unroll
            for (int g = 0; g < 3; g++) wmma::fill_fragment(acc[k8][g], 0.0f);

        // stage chunk 0 into this group's buffer 0
        {
            float av[16];
            load_a16_cg(hrow, grw, kh2, isp, mr, omr, av);
            const int b0 = AB_OFF + grp * 2 * ABUF;
            store_split16(smb + b0 + lr * SP2 + kh2,
                          smb + b0 + 5120 + lr * SP2 + kh2, av);
        }
        __syncthreads();

        for (int ch = 0; ch < 8; ch++) {
            const int cb = AB_OFF + (grp * 2 + (ch & 1)) * ABUF;
            const int nb = AB_OFF + (grp * 2 + ((ch + 1) & 1)) * ABUF;

            float av[16];
            if (ch < 7) load_a16_cg(hrow, grw, (ch + 1) * 32 + kh2, isp, mr, omr, av);

#pragma unroll
            for (int k8 = 0; k8 < 2; k8++) {
                const int kg = kg0 + ch * 32 + k8 * 16;
                wmma::fragment<wmma::matrix_a, 16, 16, 16, __nv_bfloat16, wmma::row_major> ahiF, aloF;
                wmma::load_matrix_sync(ahiF, &smb[cb + (wg * 16) * SP2 + k8 * 16], SP2);
                wmma::load_matrix_sync(aloF, &smb[cb + 5120 + (wg * 16) * SP2 + k8 * 16], SP2);
#pragma unroll
                for (int g = 0; g < 3; g++) {
                    wmma::fragment<wmma::matrix_b, 16, 16, 16, __nv_bfloat16, wmma::col_major> bhiF, bloF;
                    wmma::load_matrix_sync(bhiF, &smb[(g * 16) * WPCH + kg], WPCH);
                    wmma::load_matrix_sync(bloF, &smb[W_LO_OFF + (g * 16) * WPCH + kg], WPCH);
                    wmma::mma_sync(acc[k8][g], ahiF, bhiF, acc[k8][g]);
                    wmma::mma_sync(acc[k8][g], ahiF, bloF, acc[k8][g]);
                    wmma::mma_sync(acc[k8][g], aloF, bhiF, acc[k8][g]);
                }
            }

            if (ch < 7) {
                store_split16(smb + nb + lr * SP2 + kh2,
                              smb + nb + 5120 + lr * SP2 + kh2, av);
            }
            __syncthreads();
        }

        // merge k8-split accumulators
#pragma unroll
        for (int g = 0; g < 3; g++)
#pragma unroll
            for (int e = 0; e < acc[0][g].num_elements; e++)
                acc[0][g].x[e] += acc[1][g].x[e];

        // ---- partial C tiles to smem (overlay A region) ----
        float* Csh = Cf + grp * 128 * WSP;
#pragma unroll
        for (int g = 0; g < 3; g++)
            wmma::store_matrix_sync(&Csh[(wg * 16) * WSP + g * 16], acc[0][g], WSP,
                                    wmma::mem_row_major);
        __syncthreads();

        // ---- fused gate epilogue: row er, 4 cols at cq ----
        const float* __restrict__ C0 = Cf + er * WSP;
        const float* __restrict__ C1 = Cf + 128 * WSP + er * WSP;
        float cr[4], cz[4], cn[4];
#pragma unroll
        for (int u = 0; u < 4; u++) {
            cr[u] = C0[cq + u]      + C1[cq + u];
            cz[u] = C0[16 + cq + u] + C1[16 + cq + u];
            cn[u] = C0[32 + cq + u] + C1[32 + cq + u];
        }

        float gr_[4], gz_[4], gn_[4];
        if (!isp) {
            *(float4*)&gr_[0] = gi_r4;
            *(float4*)&gz_[0] = gi_z4;
            *(float4*)&gn_[0] = gi_n4;
        } else {
#pragma unroll
            for (int u = 0; u < 4; u++) {
                const int jc = cq + u;
                float ir = bip[jc], iz = bip[16 + jc], in_ = bip[32 + jc];
#pragma unroll
                for (int a = 0; a < 8; a++) {
                    ir  += ma8[a] * wp[jc * 8 + a];
                    iz  += ma8[a] * wp[(16 + jc) * 8 + a];
                    in_ += ma8[a] * wp[(32 + jc) * 8 + a];
                }
                gr_[u] = ir; gz_[u] = iz; gn_[u] = in_;
            }
        }

        float hv[4], hing[4];
        *(float4*)&hv[0] = hv4;
        if (isp) {
            float gg[4];
            *(float4*)&gg[0] = gg4;
#pragma unroll
            for (int u = 0; u < 4; u++) hing[u] = hv[u] * emr + gg[u] * (1.0f - emr);
        } else {
#pragma unroll
            for (int u = 0; u < 4; u++) hing[u] = hv[u] * emr;
        }

        float outv[4];
#pragma unroll
        for (int u = 0; u < 4; u++) {
            const int jc = cq + u;
            float r  = sigmoidf_(gr_[u] + cr[u] + bgs[jc]);
            float z  = sigmoidf_(gz_[u] + cz[u] + bgs[16 + jc]);
            float nn = tanhf(gn_[u] + r * (cn[u] + bgs[32 + jc]));
            outv[u] = (1.0f - z) * nn + z * hing[u];
        }
        *(float4*)(hout + (size_t)egrow * H_DIM + j0 + cq) = *(const float4*)&outv[0];

        // ---- global barrier between steps ----
        __syncthreads();
        if (tid == 0) {
            __threadfence();
            atomicAdd(&g_bar, 1u);
            const unsigned tgt = (unsigned)(t + 1) * 128u;
            unsigned v;
            do {
                asm volatile("ld.acquire.gpu.u32 %0, [%1];" : "=r"(v) : "l"(&g_bar));
                if (v < tgt) __nanosleep(32);
            } while (v < tgt);
        }
        __syncthreads();
    }
}

// ---------------------------------------------------------------------------
// Launch
// ---------------------------------------------------------------------------
extern "C" void kernel_launch(void* const* d_in, const int* in_sizes, int n_in,
                              void* d_out, int out_size) {
    const float* x        = (const float*)d_in[0];
    const float* hxs      = (const float*)d_in[1];
    const float* hys      = (const float*)d_in[2];
    const float* gru_init = (const float*)d_in[3];
    const float* masks    = (const float*)d_in[4];
    const float* pa       = (const float*)d_in[5];
    const float* w_ih     = (const float*)d_in[6];
    const float* w_hh     = (const float*)d_in[7];
    const float* b_ih     = (const float*)d_in[8];
    const float* b_hh     = (const float*)d_in[9];
    const float* w_ih_p   = (const float*)d_in[10];
    const float* w_hh_p   = (const float*)d_in[11];
    const float* b_ih_p   = (const float*)d_in[12];
    const float* b_hh_p   = (const float*)d_in[13];

    float* out      = (float*)d_out;
    float* outs     = out;                                   // (TN, H)
    float* hxs_out  = outs + (size_t)TN * H_DIM;             // (N, H)
    float* outs_p   = hxs_out + (size_t)NB * H_DIM;          // (TN, H)
    float* hys_out  = outs_p + (size_t)TN * H_DIM;           // (N, H)

    cudaFuncSetAttribute(scan_kernel, cudaFuncAttributeMaxDynamicSharedMemorySize,
                         SCAN_SMEM);

    // 1) prep
    ma_kernel<<<(TN * A_DIM + 255) / 256, 256>>>(pa, masks);
    split3_kernel<<<(G3 * K_IN / 8 + 255) / 256, 256>>>(w_ih, w_hh, w_hh_p);
    bar_reset_kernel<<<1, 1>>>();

    // 2) input GEMM: g_GI complete
    input_gemm_kernel<<<dim3(G3 / 48, TN / 256), 256>>>(x, b_ih);

    // 3) persistent scan: all 128 steps in one launch
    scan_kernel<<<128, 512, SCAN_SMEM>>>(hxs, hys, gru_init, masks,
                                         b_hh, b_hh_p, w_ih_p, b_ih_p,
                                         outs, outs_p);

    // 4) final hidden states = last timestep outputs
    cudaMemcpyAsync(hxs_out, outs   + (size_t)(T_STEPS - 1) * NB * H_DIM,
                    (size_t)NB * H_DIM * sizeof(float), cudaMemcpyDeviceToDevice);
    cudaMemcpyAsync(hys_out, outs_p + (size_t)(T_STEPS - 1) * NB * H_DIM,
                    (size_t)NB * H_DIM * sizeof(float), cudaMemcpyDeviceToDevice);
}

// round 15
// speedup vs baseline: 1.0665x; 1.0273x over previous
#include <cuda_runtime.h>
#include <cuda_bf16.h>
#include <mma.h>
#include <math.h>
#include <stdint.h>

using namespace nvcuda;

#define T_STEPS 128
#define NB      256
#define E_DIM   512
#define A_DIM   8
#define H_DIM   512
#define G3      1536
#define TN      (T_STEPS * NB)
#define K_IN    (E_DIM + A_DIM)

// ---- scratch (device globals; no dynamic allocation allowed) ----
__device__ float g_GI[(size_t)TN * G3];   // input-side gates for gru (192 MiB)
__device__ float g_MA[TN * A_DIM];        // masked prev action
__device__ unsigned g_bar;                // global barrier counter

// pre-split bf16 weights (hi/lo)
__device__ __nv_bfloat16 g_Wih_hi[G3 * K_IN],  g_Wih_lo[G3 * K_IN];
__device__ __nv_bfloat16 g_Whh_hi[G3 * H_DIM], g_Whh_lo[G3 * H_DIM];
__device__ __nv_bfloat16 g_Whp_hi[G3 * H_DIM], g_Whp_lo[G3 * H_DIM];

__device__ __forceinline__ float sigmoidf_(float x) { return 1.0f / (1.0f + expf(-x)); }

__device__ __forceinline__ void split_bf16(float v, __nv_bfloat16& hi, __nv_bfloat16& lo) {
    hi = __float2bfloat16(v);
    lo = __float2bfloat16(v - __bfloat162float(hi));
}

__device__ __forceinline__ void store_split16(__nv_bfloat16* hiDst, __nv_bfloat16* loDst,
                                              const float av[16]) {
    __nv_bfloat162 hp[8], lp[8];
#pragma unroll
    for (int u = 0; u < 8; u++) {
        __nv_bfloat16 h0, l0, h1, l1;
        split_bf16(av[2 * u],     h0, l0);
        split_bf16(av[2 * u + 1], h1, l1);
        hp[u] = __halves2bfloat162(h0, h1);
        lp[u] = __halves2bfloat162(l0, l1);
    }
    *(uint4*)(hiDst)     = *(const uint4*)&hp[0];
    *(uint4*)(hiDst + 8) = *(const uint4*)&hp[4];
    *(uint4*)(loDst)     = *(const uint4*)&lp[0];
    *(uint4*)(loDst + 8) = *(const uint4*)&lp[4];
}

// ---------------------------------------------------------------------------
// Prep kernels (round-11 exact)
// ---------------------------------------------------------------------------
__global__ void ma_kernel(const float* __restrict__ pa, const float* __restrict__ masks) {
    int i = blockIdx.x * blockDim.x + threadIdx.x;
    if (i < TN * A_DIM) g_MA[i] = pa[i] * masks[i >> 3];
}

__global__ void bar_reset_kernel() { g_bar = 0u; }

__global__ void split3_kernel(const float* __restrict__ w_ih,
                              const float* __restrict__ w_hh,
                              const float* __restrict__ w_hh_p) {
    int i8 = (blockIdx.x * blockDim.x + threadIdx.x) * 8;
    if (i8 < G3 * K_IN) {
        float4 v0 = *(const float4*)(w_ih + i8);
        float4 v1 = *(const float4*)(w_ih + i8 + 4);
        float v[8] = {v0.x, v0.y, v0.z, v0.w, v1.x, v1.y, v1.z, v1.w};
        __nv_bfloat162 hp[4], lp[4];
#pragma unroll
        for (int u = 0; u < 4; u++) {
            __nv_bfloat16 h0, l0, h1, l1;
            split_bf16(v[2 * u], h0, l0);
            split_bf16(v[2 * u + 1], h1, l1);
            hp[u] = __halves2bfloat162(h0, h1);
            lp[u] = __halves2bfloat162(l0, l1);
        }
        *(uint4*)&g_Wih_hi[i8] = *(const uint4*)&hp[0];
        *(uint4*)&g_Wih_lo[i8] = *(const uint4*)&lp[0];
    }
    if (i8 < G3 * H_DIM) {
        {
            float4 v0 = *(const float4*)(w_hh + i8);
            float4 v1 = *(const float4*)(w_hh + i8 + 4);
            float v[8] = {v0.x, v0.y, v0.z, v0.w, v1.x, v1.y, v1.z, v1.w};
            __nv_bfloat162 hp[4], lp[4];
#pragma unroll
            for (int u = 0; u < 4; u++) {
                __nv_bfloat16 h0, l0, h1, l1;
                split_bf16(v[2 * u], h0, l0);
                split_bf16(v[2 * u + 1], h1, l1);
                hp[u] = __halves2bfloat162(h0, h1);
                lp[u] = __halves2bfloat162(l0, l1);
            }
            *(uint4*)&g_Whh_hi[i8] = *(const uint4*)&hp[0];
            *(uint4*)&g_Whh_lo[i8] = *(const uint4*)&lp[0];
        }
        {
            float4 v0 = *(const float4*)(w_hh_p + i8);
            float4 v1 = *(const float4*)(w_hh_p + i8 + 4);
            float v[8] = {v0.x, v0.y, v0.z, v0.w, v1.x, v1.y, v1.z, v1.w};
            __nv_bfloat162 hp[4], lp[4];
#pragma unroll
            for (int u = 0; u < 4; u++) {
                __nv_bfloat16 h0, l0, h1, l1;
                split_bf16(v[2 * u], h0, l0);
                split_bf16(v[2 * u + 1], h1, l1);
                hp[u] = __halves2bfloat162(h0, h1);
                lp[u] = __halves2bfloat162(l0, l1);
            }
            *(uint4*)&g_Whp_hi[i8] = *(const uint4*)&hp[0];
            *(uint4*)&g_Whp_lo[i8] = *(const uint4*)&lp[0];
        }
    }
}

// ---------------------------------------------------------------------------
// Input GEMM (bf16x3 wmma): g_GI = bias + X2 @ w_ih^T
// N=96 per CTA: 256 rows x 96 gate-cols (2 j-slices x 3 gates), K=520 in 33
// chunks of 16 (chunk 32 = MA tail). A-frags reused across 6 B tiles.
// grid: (1536/96=16, 128), 256 threads. Round-11 staging pattern otherwise.
// ---------------------------------------------------------------------------
#define SP 24

__global__ void __launch_bounds__(256)
input_gemm_kernel(const float* __restrict__ X, const float* __restrict__ b_ih) {
    __shared__ __nv_bfloat16 Ahi[256 * SP], Alo[256 * SP];   // 12,288 B each
    __shared__ __nv_bfloat16 Whi[96 * SP],  Wlo[96 * SP];    // 4,608 B each
    __shared__ float btile[16 * 96];                         // 6,144 B

    const int j0 = blockIdx.x * 32;       // two 16-col j-slices
    const int m0 = blockIdx.y * 256;
    const int tid = threadIdx.x;
    const int w = tid >> 5;

    const int m = m0 + tid;
    const float* __restrict__ Xr = X + (size_t)m * E_DIM;

    // W role: tid<192, 2 threads per s-row, 8 k each
    const int sW   = tid >> 1;            // 0..95 (valid tid<192)
    const int seg8 = (tid & 1) * 8;
    const int slice = sW / 48;
    const int rem   = sW % 48;
    const int wrow  = (rem >> 4) * H_DIM + j0 + slice * 16 + (rem & 15);

    // bias tile: 16 identical rows of the 96 gate-col biases
    for (int i = tid; i < 16 * 96; i += 256) {
        int c = i % 96;
        int q2 = c >> 4;                  // 0..5: gate = q2%3, slice = q2/3
        btile[i] = b_ih[(q2 % 3) * H_DIM + j0 + (q2 / 3) * 16 + (c & 15)];
    }
    __syncthreads();

    wmma::fragment<wmma::accumulator, 16, 16, 16, float> acc[2][6];
#pragma unroll
    for (int rt = 0; rt < 2; rt++)
#pragma unroll
        for (int q2 = 0; q2 < 6; q2++)
            wmma::load_matrix_sync(acc[rt][q2], &btile[q2 * 16], 96, wmma::mem_row_major);
    __syncthreads();

    for (int ch = 0; ch < 33; ch++) {
        // stage A (round-11 pattern)
        float av[16];
        if (ch < 32) {
            const int kb = ch * 16;
            float4 a0 = *(const float4*)(Xr + kb);
            float4 a1 = *(const float4*)(Xr + kb + 4);
            float4 a2 = *(const float4*)(Xr + kb + 8);
            float4 a3 = *(const float4*)(Xr + kb + 12);
            av[0]=a0.x; av[1]=a0.y; av[2]=a0.z;  av[3]=a0.w;
            av[4]=a1.x; av[5]=a1.y; av[6]=a1.z;  av[7]=a1.w;
            av[8]=a2.x; av[9]=a2.y; av[10]=a2.z; av[11]=a2.w;
            av[12]=a3.x; av[13]=a3.y; av[14]=a3.z; av[15]=a3.w;
        } else {
            float4 m0v = *(const float4*)&g_MA[(size_t)m * A_DIM];
            float4 m1v = *(const float4*)&g_MA[(size_t)m * A_DIM + 4];
            av[0]=m0v.x; av[1]=m0v.y; av[2]=m0v.z; av[3]=m0v.w;
            av[4]=m1v.x; av[5]=m1v.y; av[6]=m1v.z; av[7]=m1v.w;
#pragma unroll
            for (int u = 8; u < 16; u++) av[u] = 0.0f;
        }
        store_split16(&Ahi[tid * SP], &Alo[tid * SP], av);

        // stage W (pre-split bf16, uint4 per thread; tail pad: k>=520 -> zeros)
        if (tid < 192) {
            const bool pad = (ch == 32) && (seg8 >= 8);
            const size_t off = (size_t)wrow * K_IN + ch * 16 + seg8;
            uint4 hv = pad ? make_uint4(0, 0, 0, 0) : *(const uint4*)(g_Wih_hi + off);
            uint4 lv = pad ? make_uint4(0, 0, 0, 0) : *(const uint4*)(g_Wih_lo + off);
            *(uint4*)&Whi[sW * SP + seg8] = hv;
            *(uint4*)&Wlo[sW * SP + seg8] = lv;
        }
        __syncthreads();

#pragma unroll
        for (int rt = 0; rt < 2; rt++) {
            wmma::fragment<wmma::matrix_a, 16, 16, 16, __nv_bfloat16, wmma::row_major> ahiF, aloF;
            wmma::load_matrix_sync(ahiF, &Ahi[(w * 32 + rt * 16) * SP], SP);
            wmma::load_matrix_sync(aloF, &Alo[(w * 32 + rt * 16) * SP], SP);
#pragma unroll
            for (int q2 = 0; q2 < 6; q2++) {
                wmma::fragment<wmma::matrix_b, 16, 16, 16, __nv_bfloat16, wmma::col_major> bhiF, bloF;
                wmma::load_matrix_sync(bhiF, &Whi[(q2 * 16) * SP], SP);
                wmma::load_matrix_sync(bloF, &Wlo[(q2 * 16) * SP], SP);
                wmma::mma_sync(acc[rt][q2], ahiF, bhiF, acc[rt][q2]);
                wmma::mma_sync(acc[rt][q2], ahiF, bloF, acc[rt][q2]);
                wmma::mma_sync(acc[rt][q2], aloF, bhiF, acc[rt][q2]);
            }
        }
        __syncthreads();
    }

#pragma unroll
    for (int rt = 0; rt < 2; rt++)
#pragma unroll
        for (int q2 = 0; q2 < 6; q2++) {
            int row0 = m0 + w * 32 + rt * 16;
            int col0 = (q2 % 3) * H_DIM + j0 + (q2 / 3) * 16;
            wmma::store_matrix_sync(g_GI + (size_t)row0 * G3 + col0, acc[rt][q2], G3,
                                    wmma::mem_row_major);
        }
}

// ---------------------------------------------------------------------------
// Persistent scan kernel — ROUND-11 EXACT (measured best). acc[3], no split.
// 128 CTAs x 512 threads, W resident in smem, global barrier between steps.
// ---------------------------------------------------------------------------
#define WPCH 520
#define SP2 40
#define WSP 56
#define W_LO_OFF 24960
#define AB_OFF   49920
#define ABUF     10240
#define SCAN_SMEM ((AB_OFF + 4 * ABUF) * 2)   // 181,760 bytes

__device__ __forceinline__ void load_a16_cg(const float* __restrict__ hrow,
                                            const float* __restrict__ grw,
                                            int kb, bool isp, float mr, float omr,
                                            float av[16]) {
    float4 h0 = __ldcg((const float4*)(hrow + kb));
    float4 h1 = __ldcg((const float4*)(hrow + kb + 4));
    float4 h2 = __ldcg((const float4*)(hrow + kb + 8));
    float4 h3 = __ldcg((const float4*)(hrow + kb + 12));
    av[0]=h0.x; av[1]=h0.y; av[2]=h0.z;  av[3]=h0.w;
    av[4]=h1.x; av[5]=h1.y; av[6]=h1.z;  av[7]=h1.w;
    av[8]=h2.x; av[9]=h2.y; av[10]=h2.z; av[11]=h2.w;
    av[12]=h3.x; av[13]=h3.y; av[14]=h3.z; av[15]=h3.w;
    if (isp) {
        float4 g0 = *(const float4*)(grw + kb);
        float4 g1 = *(const float4*)(grw + kb + 4);
        float4 g2 = *(const float4*)(grw + kb + 8);
        float4 g3 = *(const float4*)(grw + kb + 12);
        float gv[16] = {g0.x,g0.y,g0.z,g0.w, g1.x,g1.y,g1.z,g1.w,
                        g2.x,g2.y,g2.z,g2.w, g3.x,g3.y,g3.z,g3.w};
#pragma unroll
        for (int u = 0; u < 16; u++) av[u] = av[u] * mr + gv[u] * omr;
    } else {
#pragma unroll
        for (int u = 0; u < 16; u++) av[u] = av[u] * mr;
    }
}

__global__ void __launch_bounds__(512)
scan_kernel(const float* __restrict__ hxs, const float* __restrict__ hys,
            const float* __restrict__ gru_init, const float* __restrict__ masks,
            const float* __restrict__ b_hh, const float* __restrict__ b_hh_p,
            const float* __restrict__ w_ih_p, const float* __restrict__ b_ih_p,
            float* __restrict__ outs, float* __restrict__ outs_p) {
    extern __shared__ __align__(16) float dyn[];
    __shared__ float wp[48 * 8];
    __shared__ float bgs[48];
    __shared__ float bip[48];

    __nv_bfloat16* smb = (__nv_bfloat16*)dyn;
    float* Cf = dyn + W_LO_OFF;

    const int cta = blockIdx.x;
    const bool isp = (cta >= 64);
    const int q = cta & 63;
    const int j0 = (q >> 1) * 16;
    const int mbase = (q & 1) * 128;

    const __nv_bfloat16* __restrict__ WhiG = isp ? g_Whp_hi : g_Whh_hi;
    const __nv_bfloat16* __restrict__ WloG = isp ? g_Whp_lo : g_Whh_lo;
    const float* __restrict__ bh = isp ? b_hh_p : b_hh;

    const int tid = threadIdx.x;
    const int grp  = tid >> 8;
    const int gtid = tid & 255;
    const int wg   = (tid >> 5) & 7;
    const int kg0  = grp * 256;

    const int lr  = gtid >> 1;
    const int kh2 = (gtid & 1) * 16;
    const int grow = mbase + lr;
    const int er  = tid >> 2;
    const int cq  = (tid & 3) * 4;
    const int egrow = mbase + er;

    // ---- one-time setup: stage W resident, biases, wp ----
    for (int i = tid; i < 48 * 64; i += 512) {
        const int r = i >> 6, s8 = (i & 63) * 8;
        const int wr = (r >> 4) * H_DIM + j0 + (r & 15);
        *(uint4*)&smb[r * WPCH + s8]            = *(const uint4*)&WhiG[(size_t)wr * H_DIM + s8];
        *(uint4*)&smb[W_LO_OFF + r * WPCH + s8] = *(const uint4*)&WloG[(size_t)wr * H_DIM + s8];
    }
    if (tid < 48) {
        const int gidx = (tid >> 4) * H_DIM + j0 + (tid & 15);
        bgs[tid] = bh[gidx];
        bip[tid] = b_ih_p[gidx];
    }
    if (tid < 96) {
        const int s = tid >> 1, hf = (tid & 1) * 4;
        const int gidx = (s >> 4) * H_DIM + j0 + (s & 15);
        *(float4*)&wp[s * 8 + hf] = *(const float4*)&w_ih_p[(size_t)gidx * A_DIM + hf];
    }
    __syncthreads();

    for (int t = 0; t < T_STEPS; t++) {
        const float* __restrict__ hxp = t ? outs   + (size_t)(t - 1) * NB * H_DIM : hxs;
        const float* __restrict__ hyp = t ? outs_p + (size_t)(t - 1) * NB * H_DIM : hys;
        const float* __restrict__ hp = isp ? hyp : hxp;
        float* __restrict__ hout = (isp ? outs_p : outs) + (size_t)t * NB * H_DIM;
        const float* __restrict__ masks_t = masks + t * NB;
        const float* __restrict__ g_t = gru_init + (size_t)t * NB * H_DIM;

        const float mr = masks_t[grow];
        const float omr = 1.0f - mr;
        const float* __restrict__ hrow = hp  + (size_t)grow * H_DIM + kg0;
        const float* __restrict__ grw  = g_t + (size_t)grow * H_DIM + kg0;

        // ---- epilogue prefetch ----
        const float emr = masks_t[egrow];
        float4 hv4 = __ldcg((const float4*)(hp + (size_t)egrow * H_DIM + j0 + cq));
        float4 gg4, gi_r4, gi_z4, gi_n4;
        float ma8[8];
        if (isp) {
            gg4 = *(const float4*)(g_t + (size_t)egrow * H_DIM + j0 + cq);
            float4 m0 = *(const float4*)&g_MA[((size_t)t * NB + egrow) * A_DIM];
            float4 m1 = *(const float4*)&g_MA[((size_t)t * NB + egrow) * A_DIM + 4];
            ma8[0]=m0.x; ma8[1]=m0.y; ma8[2]=m0.z; ma8[3]=m0.w;
            ma8[4]=m1.x; ma8[5]=m1.y; ma8[6]=m1.z; ma8[7]=m1.w;
        } else {
            const float* __restrict__ gi = g_GI + ((size_t)t * NB + egrow) * G3 + j0;
            gi_r4 = *(const float4*)(gi + cq);
            gi_z4 = *(const float4*)(gi + 512 + cq);
            gi_n4 = *(const float4*)(gi + 1024 + cq);
        }

        wmma::fragment<wmma::accumulator, 16, 16, 16, float> acc[3];
#pragma unroll
        for (int g = 0; g < 3; g++) wmma::fill_fragment(acc[g], 0.0f);

        // stage chunk 0 into this group's buffer 0
        {
            float av[16];
            load_a16_cg(hrow, grw, kh2, isp, mr, omr, av);
            const int b0 = AB_OFF + grp * 2 * ABUF;
            store_split16(smb + b0 + lr * SP2 + kh2,
                          smb + b0 + 5120 + lr * SP2 + kh2, av);
        }
        __syncthreads();

        for (int ch = 0; ch < 8; ch++) {
            const int cb = AB_OFF + (grp * 2 + (ch & 1)) * ABUF;
            const int nb = AB_OFF + (grp * 2 + ((ch + 1) & 1)) * ABUF;

            float av[16];
            if (ch < 7) load_a16_cg(hrow, grw, (ch + 1) * 32 + kh2, isp, mr, omr, av);

#pragma unroll
            for (int k8 = 0; k8 < 2; k8++) {
                const int kg = kg0 + ch * 32 + k8 * 16;
                wmma::fragment<wmma::matrix_a, 16, 16, 16, __nv_bfloat16, wmma::row_major> ahiF, aloF;
                wmma::load_matrix_sync(ahiF, &smb[cb + (wg * 16) * SP2 + k8 * 16], SP2);
                wmma::load_matrix_sync(aloF, &smb[cb + 5120 + (wg * 16) * SP2 + k8 * 16], SP2);
#pragma unroll
                for (int g = 0; g < 3; g++) {
                    wmma::fragment<wmma::matrix_b, 16, 16, 16, __nv_bfloat16, wmma::col_major> bhiF, bloF;
                    wmma::load_matrix_sync(bhiF, &smb[(g * 16) * WPCH + kg], WPCH);
                    wmma::load_matrix_sync(bloF, &smb[W_LO_OFF + (g * 16) * WPCH + kg], WPCH);
                    wmma::mma_sync(acc[g], ahiF, bhiF, acc[g]);
                    wmma::mma_sync(acc[g], ahiF, bloF, acc[g]);
                    wmma::mma_sync(acc[g], aloF, bhiF, acc[g]);
                }
            }

            if (ch < 7) {
                store_split16(smb + nb + lr * SP2 + kh2,
                              smb + nb + 5120 + lr * SP2 + kh2, av);
            }
            __syncthreads();
        }

        // ---- partial C tiles to smem (overlay A region) ----
        float* Csh = Cf + grp * 128 * WSP;
#pragma unroll
        for (int g = 0; g < 3; g++)
            wmma::store_matrix_sync(&Csh[(wg * 16) * WSP + g * 16], acc[g], WSP,
                                    wmma::mem_row_major);
        __syncthreads();

        // ---- fused gate epilogue: row er, 4 cols at cq ----
        const float* __restrict__ C0 = Cf + er * WSP;
        const float* __restrict__ C1 = Cf + 128 * WSP + er * WSP;
        float cr[4], cz[4], cn[4];
#pragma unroll
        for (int u = 0; u < 4; u++) {
            cr[u] = C0[cq + u]      + C1[cq + u];
            cz[u] = C0[16 + cq + u] + C1[16 + cq + u];
            cn[u] = C0[32 + cq + u] + C1[32 + cq + u];
        }

        float gr_[4], gz_[4], gn_[4];
        if (!isp) {
            *(float4*)&gr_[0] = gi_r4;
            *(float4*)&gz_[0] = gi_z4;
            *(float4*)&gn_[0] = gi_n4;
        } else {
#pragma unroll
            for (int u = 0; u < 4; u++) {
                const int jc = cq + u;
                float ir = bip[jc], iz = bip[16 + jc], in_ = bip[32 + jc];
#pragma unroll
                for (int a = 0; a < 8; a++) {
                    ir  += ma8[a] * wp[jc * 8 + a];
                    iz  += ma8[a] * wp[(16 + jc) * 8 + a];
                    in_ += ma8[a] * wp[(32 + jc) * 8 + a];
                }
                gr_[u] = ir; gz_[u] = iz; gn_[u] = in_;
            }
        }

        float hv[4], hing[4];
        *(float4*)&hv[0] = hv4;
        if (isp) {
            float gg[4];
            *(float4*)&gg[0] = gg4;
#pragma unroll
            for (int u = 0; u < 4; u++) hing[u] = hv[u] * emr + gg[u] * (1.0f - emr);
        } else {
#pragma unroll
            for (int u = 0; u < 4; u++) hing[u] = hv[u] * emr;
        }

        float outv[4];
#pragma unroll
        for (int u = 0; u < 4; u++) {
            const int jc = cq + u;
            float r  = sigmoidf_(gr_[u] + cr[u] + bgs[jc]);
            float z  = sigmoidf_(gz_[u] + cz[u] + bgs[16 + jc]);
            float nn = tanhf(gn_[u] + r * (cn[u] + bgs[32 + jc]));
            outv[u] = (1.0f - z) * nn + z * hing[u];
        }
        *(float4*)(hout + (size_t)egrow * H_DIM + j0 + cq) = *(const float4*)&outv[0];

        // ---- global barrier between steps ----
        __syncthreads();
        if (tid == 0) {
            __threadfence();
            atomicAdd(&g_bar, 1u);
            const unsigned tgt = (unsigned)(t + 1) * 128u;
            unsigned v;
            do {
                asm volatile("ld.acquire.gpu.u32 %0, [%1];" : "=r"(v) : "l"(&g_bar));
                if (v < tgt) __nanosleep(32);
            } while (v < tgt);
        }
        __syncthreads();
    }
}

// ---------------------------------------------------------------------------
// Launch
// ---------------------------------------------------------------------------
extern "C" void kernel_launch(void* const* d_in, const int* in_sizes, int n_in,
                              void* d_out, int out_size) {
    const float* x        = (const float*)d_in[0];
    const float* hxs      = (const float*)d_in[1];
    const float* hys      = (const float*)d_in[2];
    const float* gru_init = (const float*)d_in[3];
    const float* masks    = (const float*)d_in[4];
    const float* pa       = (const float*)d_in[5];
    const float* w_ih     = (const float*)d_in[6];
    const float* w_hh     = (const float*)d_in[7];
    const float* b_ih     = (const float*)d_in[8];
    const float* b_hh     = (const float*)d_in[9];
    const float* w_ih_p   = (const float*)d_in[10];
    const float* w_hh_p   = (const float*)d_in[11];
    const float* b_ih_p   = (const float*)d_in[12];
    const float* b_hh_p   = (const float*)d_in[13];

    float* out      = (float*)d_out;
    float* outs     = out;                                   // (TN, H)
    float* hxs_out  = outs + (size_t)TN * H_DIM;             // (N, H)
    float* outs_p   = hxs_out + (size_t)NB * H_DIM;          // (TN, H)
    float* hys_out  = outs_p + (size_t)TN * H_DIM;           // (N, H)

    cudaFuncSetAttribute(scan_kernel, cudaFuncAttributeMaxDynamicSharedMemorySize,
                         SCAN_SMEM);

    // 1) prep
    ma_kernel<<<(TN * A_DIM + 255) / 256, 256>>>(pa, masks);
    split3_kernel<<<(G3 * K_IN / 8 + 255) / 256, 256>>>(w_ih, w_hh, w_hh_p);
    bar_reset_kernel<<<1, 1>>>();

    // 2) input GEMM: g_GI complete (N=96 per CTA)
    input_gemm_kernel<<<dim3(G3 / 96, TN / 256), 256>>>(x, b_ih);

    // 3) persistent scan: all 128 steps in one launch
    scan_kernel<<<128, 512, SCAN_SMEM>>>(hxs, hys, gru_init, masks,
                                         b_hh, b_hh_p, w_ih_p, b_ih_p,
                                         outs, outs_p);

    // 4) final hidden states = last timestep outputs
    cudaMemcpyAsync(hxs_out, outs   + (size_t)(T_STEPS - 1) * NB * H_DIM,
                    (size_t)NB * H_DIM * sizeof(float), cudaMemcpyDeviceToDevice);
    cudaMemcpyAsync(hys_out, outs_p + (size_t)(T_STEPS - 1) * NB * H_DIM,
                    (size_t)NB * H_DIM * sizeof(float), cudaMemcpyDeviceToDevice);
}

// round 16
// speedup vs baseline: 1.0724x; 1.0055x over previous
#include <cuda_runtime.h>
#include <cuda_bf16.h>
#include <mma.h>
#include <math.h>
#include <stdint.h>

using namespace nvcuda;

#define T_STEPS 128
#define NB      256
#define E_DIM   512
#define A_DIM   8
#define H_DIM   512
#define G3      1536
#define TN      (T_STEPS * NB)
#define K_IN    (E_DIM + A_DIM)

// ---- scratch (device globals; no dynamic allocation allowed) ----
__device__ float g_GI[(size_t)TN * G3];   // input-side gates for gru (192 MiB)
__device__ float g_MA[TN * A_DIM];        // masked prev action
__device__ unsigned g_bar;                // global barrier counter

// pre-split bf16 weights (hi/lo)
__device__ __nv_bfloat16 g_Wih_hi[G3 * K_IN],  g_Wih_lo[G3 * K_IN];
__device__ __nv_bfloat16 g_Whh_hi[G3 * H_DIM], g_Whh_lo[G3 * H_DIM];
__device__ __nv_bfloat16 g_Whp_hi[G3 * H_DIM], g_Whp_lo[G3 * H_DIM];

__device__ __forceinline__ float sigmoidf_(float x) { return 1.0f / (1.0f + expf(-x)); }

__device__ __forceinline__ void split_bf16(float v, __nv_bfloat16& hi, __nv_bfloat16& lo) {
    hi = __float2bfloat16(v);
    lo = __float2bfloat16(v - __bfloat162float(hi));
}

__device__ __forceinline__ void store_split16(__nv_bfloat16* hiDst, __nv_bfloat16* loDst,
                                              const float av[16]) {
    __nv_bfloat162 hp[8], lp[8];
#pragma unroll
    for (int u = 0; u < 8; u++) {
        __nv_bfloat16 h0, l0, h1, l1;
        split_bf16(av[2 * u],     h0, l0);
        split_bf16(av[2 * u + 1], h1, l1);
        hp[u] = __halves2bfloat162(h0, h1);
        lp[u] = __halves2bfloat162(l0, l1);
    }
    *(uint4*)(hiDst)     = *(const uint4*)&hp[0];
    *(uint4*)(hiDst + 8) = *(const uint4*)&hp[4];
    *(uint4*)(loDst)     = *(const uint4*)&lp[0];
    *(uint4*)(loDst + 8) = *(const uint4*)&lp[4];
}

// ---------------------------------------------------------------------------
// Prep kernels (round-11 exact)
// ---------------------------------------------------------------------------
__global__ void ma_kernel(const float* __restrict__ pa, const float* __restrict__ masks) {
    int i = blockIdx.x * blockDim.x + threadIdx.x;
    if (i < TN * A_DIM) g_MA[i] = pa[i] * masks[i >> 3];
}

__global__ void bar_reset_kernel() { g_bar = 0u; }

__global__ void split3_kernel(const float* __restrict__ w_ih,
                              const float* __restrict__ w_hh,
                              const float* __restrict__ w_hh_p) {
    int i8 = (blockIdx.x * blockDim.x + threadIdx.x) * 8;
    if (i8 < G3 * K_IN) {
        float4 v0 = *(const float4*)(w_ih + i8);
        float4 v1 = *(const float4*)(w_ih + i8 + 4);
        float v[8] = {v0.x, v0.y, v0.z, v0.w, v1.x, v1.y, v1.z, v1.w};
        __nv_bfloat162 hp[4], lp[4];
#pragma unroll
        for (int u = 0; u < 4; u++) {
            __nv_bfloat16 h0, l0, h1, l1;
            split_bf16(v[2 * u], h0, l0);
            split_bf16(v[2 * u + 1], h1, l1);
            hp[u] = __halves2bfloat162(h0, h1);
            lp[u] = __halves2bfloat162(l0, l1);
        }
        *(uint4*)&g_Wih_hi[i8] = *(const uint4*)&hp[0];
        *(uint4*)&g_Wih_lo[i8] = *(const uint4*)&lp[0];
    }
    if (i8 < G3 * H_DIM) {
        {
            float4 v0 = *(const float4*)(w_hh + i8);
            float4 v1 = *(const float4*)(w_hh + i8 + 4);
            float v[8] = {v0.x, v0.y, v0.z, v0.w, v1.x, v1.y, v1.z, v1.w};
            __nv_bfloat162 hp[4], lp[4];
#pragma unroll
            for (int u = 0; u < 4; u++) {
                __nv_bfloat16 h0, l0, h1, l1;
                split_bf16(v[2 * u], h0, l0);
                split_bf16(v[2 * u + 1], h1, l1);
                hp[u] = __halves2bfloat162(h0, h1);
                lp[u] = __halves2bfloat162(l0, l1);
            }
            *(uint4*)&g_Whh_hi[i8] = *(const uint4*)&hp[0];
            *(uint4*)&g_Whh_lo[i8] = *(const uint4*)&lp[0];
        }
        {
            float4 v0 = *(const float4*)(w_hh_p + i8);
            float4 v1 = *(const float4*)(w_hh_p + i8 + 4);
            float v[8] = {v0.x, v0.y, v0.z, v0.w, v1.x, v1.y, v1.z, v1.w};
            __nv_bfloat162 hp[4], lp[4];
#pragma unroll
            for (int u = 0; u < 4; u++) {
                __nv_bfloat16 h0, l0, h1, l1;
                split_bf16(v[2 * u], h0, l0);
                split_bf16(v[2 * u + 1], h1, l1);
                hp[u] = __halves2bfloat162(h0, h1);
                lp[u] = __halves2bfloat162(l0, l1);
            }
            *(uint4*)&g_Whp_hi[i8] = *(const uint4*)&hp[0];
            *(uint4*)&g_Whp_lo[i8] = *(const uint4*)&lp[0];
        }
    }
}

// ---------------------------------------------------------------------------
// Input GEMM (bf16x3 wmma): round-11 structure with fragment-load hoisting.
// CTA: 256 rows x 48 gate-cols, K=520 in 33 chunks of 16 (chunk 32 = MA tail).
// Per chunk: preload A-frags (both row tiles), then per B tile load once and
// feed both row tiles (B LDSM traffic halved vs round-11).
// grid: (32, 128), 256 threads.
// ---------------------------------------------------------------------------
#define SP 24

__global__ void __launch_bounds__(256)
input_gemm_kernel(const float* __restrict__ X, const float* __restrict__ b_ih) {
    __shared__ __nv_bfloat16 Ahi[256 * SP], Alo[256 * SP];
    __shared__ __nv_bfloat16 Whi[48 * SP],  Wlo[48 * SP];
    __shared__ float btile[16 * 48];

    const int j0 = blockIdx.x * 16;
    const int m0 = blockIdx.y * 256;
    const int tid = threadIdx.x;
    const int w = tid >> 5;

    const int m = m0 + tid;
    const float* __restrict__ Xr = X + (size_t)m * E_DIM;
    const int sW = tid >> 2;
    const int segW = (tid & 3) * 4;
    const int wrow = (sW >> 4) * H_DIM + j0 + (sW & 15);

    for (int i = tid; i < 16 * 48; i += 256) {
        int c = i % 48;
        btile[i] = b_ih[(c >> 4) * H_DIM + j0 + (c & 15)];
    }
    __syncthreads();

    wmma::fragment<wmma::accumulator, 16, 16, 16, float> acc[2][3];
#pragma unroll
    for (int rt = 0; rt < 2; rt++)
#pragma unroll
        for (int g = 0; g < 3; g++)
            wmma::load_matrix_sync(acc[rt][g], &btile[g * 16], 48, wmma::mem_row_major);
    __syncthreads();

    for (int ch = 0; ch < 33; ch++) {
        float av[16];
        if (ch < 32) {
            const int kb = ch * 16;
            float4 a0 = *(const float4*)(Xr + kb);
            float4 a1 = *(const float4*)(Xr + kb + 4);
            float4 a2 = *(const float4*)(Xr + kb + 8);
            float4 a3 = *(const float4*)(Xr + kb + 12);
            av[0]=a0.x; av[1]=a0.y; av[2]=a0.z;  av[3]=a0.w;
            av[4]=a1.x; av[5]=a1.y; av[6]=a1.z;  av[7]=a1.w;
            av[8]=a2.x; av[9]=a2.y; av[10]=a2.z; av[11]=a2.w;
            av[12]=a3.x; av[13]=a3.y; av[14]=a3.z; av[15]=a3.w;
        } else {
            float4 m0v = *(const float4*)&g_MA[(size_t)m * A_DIM];
            float4 m1v = *(const float4*)&g_MA[(size_t)m * A_DIM + 4];
            av[0]=m0v.x; av[1]=m0v.y; av[2]=m0v.z; av[3]=m0v.w;
            av[4]=m1v.x; av[5]=m1v.y; av[6]=m1v.z; av[7]=m1v.w;
#pragma unroll
            for (int u = 8; u < 16; u++) av[u] = 0.0f;
        }
        store_split16(&Ahi[tid * SP], &Alo[tid * SP], av);

        if (tid < 192) {
            const bool pad = (ch == 32) && (segW >= 8);
            const size_t off = (size_t)wrow * K_IN + ch * 16 + segW;
            uint2 hv = pad ? make_uint2(0, 0) : *(const uint2*)(g_Wih_hi + off);
            uint2 lv = pad ? make_uint2(0, 0) : *(const uint2*)(g_Wih_lo + off);
            *(uint2*)&Whi[sW * SP + segW] = hv;
            *(uint2*)&Wlo[sW * SP + segW] = lv;
        }
        __syncthreads();

        // --- hoisted fragment loads: A-frags once per row-tile, B once per tile ---
        wmma::fragment<wmma::matrix_a, 16, 16, 16, __nv_bfloat16, wmma::row_major> ahiF[2], aloF[2];
#pragma unroll
        for (int rt = 0; rt < 2; rt++) {
            wmma::load_matrix_sync(ahiF[rt], &Ahi[(w * 32 + rt * 16) * SP], SP);
            wmma::load_matrix_sync(aloF[rt], &Alo[(w * 32 + rt * 16) * SP], SP);
        }
#pragma unroll
        for (int g = 0; g < 3; g++) {
            wmma::fragment<wmma::matrix_b, 16, 16, 16, __nv_bfloat16, wmma::col_major> bhiF, bloF;
            wmma::load_matrix_sync(bhiF, &Whi[(g * 16) * SP], SP);
            wmma::load_matrix_sync(bloF, &Wlo[(g * 16) * SP], SP);
#pragma unroll
            for (int rt = 0; rt < 2; rt++) {
                wmma::mma_sync(acc[rt][g], ahiF[rt], bhiF, acc[rt][g]);
                wmma::mma_sync(acc[rt][g], ahiF[rt], bloF, acc[rt][g]);
                wmma::mma_sync(acc[rt][g], aloF[rt], bhiF, acc[rt][g]);
            }
        }
        __syncthreads();
    }

#pragma unroll
    for (int rt = 0; rt < 2; rt++)
#pragma unroll
        for (int g = 0; g < 3; g++) {
            int row0 = m0 + w * 32 + rt * 16;
            int col0 = g * H_DIM + j0;
            wmma::store_matrix_sync(g_GI + (size_t)row0 * G3 + col0, acc[rt][g], G3,
                                    wmma::mem_row_major);
        }
}

// ---------------------------------------------------------------------------
// Persistent scan kernel — ROUND-11 EXACT (measured best).
// 128 CTAs x 512 threads, W resident in smem, global barrier between steps.
// ---------------------------------------------------------------------------
#define WPCH 520
#define SP2 40
#define WSP 56
#define W_LO_OFF 24960
#define AB_OFF   49920
#define ABUF     10240
#define SCAN_SMEM ((AB_OFF + 4 * ABUF) * 2)   // 181,760 bytes

__device__ __forceinline__ void load_a16_cg(const float* __restrict__ hrow,
                                            const float* __restrict__ grw,
                                            int kb, bool isp, float mr, float omr,
                                            float av[16]) {
    float4 h0 = __ldcg((const float4*)(hrow + kb));
    float4 h1 = __ldcg((const float4*)(hrow + kb + 4));
    float4 h2 = __ldcg((const float4*)(hrow + kb + 8));
    float4 h3 = __ldcg((const float4*)(hrow + kb + 12));
    av[0]=h0.x; av[1]=h0.y; av[2]=h0.z;  av[3]=h0.w;
    av[4]=h1.x; av[5]=h1.y; av[6]=h1.z;  av[7]=h1.w;
    av[8]=h2.x; av[9]=h2.y; av[10]=h2.z; av[11]=h2.w;
    av[12]=h3.x; av[13]=h3.y; av[14]=h3.z; av[15]=h3.w;
    if (isp) {
        float4 g0 = *(const float4*)(grw + kb);
        float4 g1 = *(const float4*)(grw + kb + 4);
        float4 g2 = *(const float4*)(grw + kb + 8);
        float4 g3 = *(const float4*)(grw + kb + 12);
        float gv[16] = {g0.x,g0.y,g0.z,g0.w, g1.x,g1.y,g1.z,g1.w,
                        g2.x,g2.y,g2.z,g2.w, g3.x,g3.y,g3.z,g3.w};
#pragma unroll
        for (int u = 0; u < 16; u++) av[u] = av[u] * mr + gv[u] * omr;
    } else {
#pragma unroll
        for (int u = 0; u < 16; u++) av[u] = av[u] * mr;
    }
}

__global__ void __launch_bounds__(512)
scan_kernel(const float* __restrict__ hxs, const float* __restrict__ hys,
            const float* __restrict__ gru_init, const float* __restrict__ masks,
            const float* __restrict__ b_hh, const float* __restrict__ b_hh_p,
            const float* __restrict__ w_ih_p, const float* __restrict__ b_ih_p,
            float* __restrict__ outs, float* __restrict__ outs_p) {
    extern __shared__ __align__(16) float dyn[];
    __shared__ float wp[48 * 8];
    __shared__ float bgs[48];
    __shared__ float bip[48];

    __nv_bfloat16* smb = (__nv_bfloat16*)dyn;
    float* Cf = dyn + W_LO_OFF;

    const int cta = blockIdx.x;
    const bool isp = (cta >= 64);
    const int q = cta & 63;
    const int j0 = (q >> 1) * 16;
    const int mbase = (q & 1) * 128;

    const __nv_bfloat16* __restrict__ WhiG = isp ? g_Whp_hi : g_Whh_hi;
    const __nv_bfloat16* __restrict__ WloG = isp ? g_Whp_lo : g_Whh_lo;
    const float* __restrict__ bh = isp ? b_hh_p : b_hh;

    const int tid = threadIdx.x;
    const int grp  = tid >> 8;
    const int gtid = tid & 255;
    const int wg   = (tid >> 5) & 7;
    const int kg0  = grp * 256;

    const int lr  = gtid >> 1;
    const int kh2 = (gtid & 1) * 16;
    const int grow = mbase + lr;
    const int er  = tid >> 2;
    const int cq  = (tid & 3) * 4;
    const int egrow = mbase + er;

    // ---- one-time setup: stage W resident, biases, wp ----
    for (int i = tid; i < 48 * 64; i += 512) {
        const int r = i >> 6, s8 = (i & 63) * 8;
        const int wr = (r >> 4) * H_DIM + j0 + (r & 15);
        *(uint4*)&smb[r * WPCH + s8]            = *(const uint4*)&WhiG[(size_t)wr * H_DIM + s8];
        *(uint4*)&smb[W_LO_OFF + r * WPCH + s8] = *(const uint4*)&WloG[(size_t)wr * H_DIM + s8];
    }
    if (tid < 48) {
        const int gidx = (tid >> 4) * H_DIM + j0 + (tid & 15);
        bgs[tid] = bh[gidx];
        bip[tid] = b_ih_p[gidx];
    }
    if (tid < 96) {
        const int s = tid >> 1, hf = (tid & 1) * 4;
        const int gidx = (s >> 4) * H_DIM + j0 + (s & 15);
        *(float4*)&wp[s * 8 + hf] = *(const float4*)&w_ih_p[(size_t)gidx * A_DIM + hf];
    }
    __syncthreads();

    for (int t = 0; t < T_STEPS; t++) {
        const float* __restrict__ hxp = t ? outs   + (size_t)(t - 1) * NB * H_DIM : hxs;
        const float* __restrict__ hyp = t ? outs_p + (size_t)(t - 1) * NB * H_DIM : hys;
        const float* __restrict__ hp = isp ? hyp : hxp;
        float* __restrict__ hout = (isp ? outs_p : outs) + (size_t)t * NB * H_DIM;
        const float* __restrict__ masks_t = masks + t * NB;
        const float* __restrict__ g_t = gru_init + (size_t)t * NB * H_DIM;

        const float mr = masks_t[grow];
        const float omr = 1.0f - mr;
        const float* __restrict__ hrow = hp  + (size_t)grow * H_DIM + kg0;
        const float* __restrict__ grw  = g_t + (size_t)grow * H_DIM + kg0;

        // ---- epilogue prefetch ----
        const float emr = masks_t[egrow];
        float4 hv4 = __ldcg((const float4*)(hp + (size_t)egrow * H_DIM + j0 + cq));
        float4 gg4, gi_r4, gi_z4, gi_n4;
        float ma8[8];
        if (isp) {
            gg4 = *(const float4*)(g_t + (size_t)egrow * H_DIM + j0 + cq);
            float4 m0 = *(const float4*)&g_MA[((size_t)t * NB + egrow) * A_DIM];
            float4 m1 = *(const float4*)&g_MA[((size_t)t * NB + egrow) * A_DIM + 4];
            ma8[0]=m0.x; ma8[1]=m0.y; ma8[2]=m0.z; ma8[3]=m0.w;
            ma8[4]=m1.x; ma8[5]=m1.y; ma8[6]=m1.z; ma8[7]=m1.w;
        } else {
            const float* __restrict__ gi = g_GI + ((size_t)t * NB + egrow) * G3 + j0;
            gi_r4 = *(const float4*)(gi + cq);
            gi_z4 = *(const float4*)(gi + 512 + cq);
            gi_n4 = *(const float4*)(gi + 1024 + cq);
        }

        wmma::fragment<wmma::accumulator, 16, 16, 16, float> acc[3];
#pragma unroll
        for (int g = 0; g < 3; g++) wmma::fill_fragment(acc[g], 0.0f);

        // stage chunk 0 into this group's buffer 0
        {
            float av[16];
            load_a16_cg(hrow, grw, kh2, isp, mr, omr, av);
            const int b0 = AB_OFF + grp * 2 * ABUF;
            store_split16(smb + b0 + lr * SP2 + kh2,
                          smb + b0 + 5120 + lr * SP2 + kh2, av);
        }
        __syncthreads();

        for (int ch = 0; ch < 8; ch++) {
            const int cb = AB_OFF + (grp * 2 + (ch & 1)) * ABUF;
            const int nb = AB_OFF + (grp * 2 + ((ch + 1) & 1)) * ABUF;

            float av[16];
            if (ch < 7) load_a16_cg(hrow, grw, (ch + 1) * 32 + kh2, isp, mr, omr, av);

#pragma unroll
            for (int k8 = 0; k8 < 2; k8++) {
                const int kg = kg0 + ch * 32 + k8 * 16;
                wmma::fragment<wmma::matrix_a, 16, 16, 16, __nv_bfloat16, wmma::row_major> ahiF, aloF;
                wmma::load_matrix_sync(ahiF, &smb[cb + (wg * 16) * SP2 + k8 * 16], SP2);
                wmma::load_matrix_sync(aloF, &smb[cb + 5120 + (wg * 16) * SP2 + k8 * 16], SP2);
#pragma unroll
                for (int g = 0; g < 3; g++) {
                    wmma::fragment<wmma::matrix_b, 16, 16, 16, __nv_bfloat16, wmma::col_major> bhiF, bloF;
                    wmma::load_matrix_sync(bhiF, &smb[(g * 16) * WPCH + kg], WPCH);
                    wmma::load_matrix_sync(bloF, &smb[W_LO_OFF + (g * 16) * WPCH + kg], WPCH);
                    wmma::mma_sync(acc[g], ahiF, bhiF, acc[g]);
                    wmma::mma_sync(acc[g], ahiF, bloF, acc[g]);
                    wmma::mma_sync(acc[g], aloF, bhiF, acc[g]);
                }
            }

            if (ch < 7) {
                store_split16(smb + nb + lr * SP2 + kh2,
                              smb + nb + 5120 + lr * SP2 + kh2, av);
            }
            __syncthreads();
        }

        // ---- partial C tiles to smem (overlay A region) ----
        float* Csh = Cf + grp * 128 * WSP;
#pragma unroll
        for (int g = 0; g < 3; g++)
            wmma::store_matrix_sync(&Csh[(wg * 16) * WSP + g * 16], acc[g], WSP,
                                    wmma::mem_row_major);
        __syncthreads();

        // ---- fused gate epilogue: row er, 4 cols at cq ----
        const float* __restrict__ C0 = Cf + er * WSP;
        const float* __restrict__ C1 = Cf + 128 * WSP + er * WSP;
        float cr[4], cz[4], cn[4];
#pragma unroll
        for (int u = 0; u < 4; u++) {
            cr[u] = C0[cq + u]      + C1[cq + u];
            cz[u] = C0[16 + cq + u] + C1[16 + cq + u];
            cn[u] = C0[32 + cq + u] + C1[32 + cq + u];
        }

        float gr_[4], gz_[4], gn_[4];
        if (!isp) {
            *(float4*)&gr_[0] = gi_r4;
            *(float4*)&gz_[0] = gi_z4;
            *(float4*)&gn_[0] = gi_n4;
        } else {
#pragma unroll
            for (int u = 0; u < 4; u++) {
                const int jc = cq + u;
                float ir = bip[jc], iz = bip[16 + jc], in_ = bip[32 + jc];
#pragma unroll
                for (int a = 0; a < 8; a++) {
                    ir  += ma8[a] * wp[jc * 8 + a];
                    iz  += ma8[a] * wp[(16 + jc) * 8 + a];
                    in_ += ma8[a] * wp[(32 + jc) * 8 + a];
                }
                gr_[u] = ir; gz_[u] = iz; gn_[u] = in_;
            }
        }

        float hv[4], hing[4];
        *(float4*)&hv[0] = hv4;
        if (isp) {
            float gg[4];
            *(float4*)&gg[0] = gg4;
#pragma unroll
            for (int u = 0; u < 4; u++) hing[u] = hv[u] * emr + gg[u] * (1.0f - emr);
        } else {
#pragma unroll
            for (int u = 0; u < 4; u++) hing[u] = hv[u] * emr;
        }

        float outv[4];
#pragma unroll
        for (int u = 0; u < 4; u++) {
            const int jc = cq + u;
            float r  = sigmoidf_(gr_[u] + cr[u] + bgs[jc]);
            float z  = sigmoidf_(gz_[u] + cz[u] + bgs[16 + jc]);
            float nn = tanhf(gn_[u] + r * (cn[u] + bgs[32 + jc]));
            outv[u] = (1.0f - z) * nn + z * hing[u];
        }
        *(float4*)(hout + (size_t)egrow * H_DIM + j0 + cq) = *(const float4*)&outv[0];

        // ---- global barrier between steps ----
        __syncthreads();
        if (tid == 0) {
            __threadfence();
            atomicAdd(&g_bar, 1u);
            const unsigned tgt = (unsigned)(t + 1) * 128u;
            unsigned v;
            do {
                asm volatile("ld.acquire.gpu.u32 %0, [%1];" : "=r"(v) : "l"(&g_bar));
                if (v < tgt) __nanosleep(32);
            } while (v < tgt);
        }
        __syncthreads();
    }
}

// ---------------------------------------------------------------------------
// Launch
// ---------------------------------------------------------------------------
extern "C" void kernel_launch(void* const* d_in, const int* in_sizes, int n_in,
                              void* d_out, int out_size) {
    const float* x        = (const float*)d_in[0];
    const float* hxs      = (const float*)d_in[1];
    const float* hys      = (const float*)d_in[2];
    const float* gru_init = (const float*)d_in[3];
    const float* masks    = (const float*)d_in[4];
    const float* pa       = (const float*)d_in[5];
    const float* w_ih     = (const float*)d_in[6];
    const float* w_hh     = (const float*)d_in[7];
    const float* b_ih     = (const float*)d_in[8];
    const float* b_hh     = (const float*)d_in[9];
    const float* w_ih_p   = (const float*)d_in[10];
    const float* w_hh_p   = (const float*)d_in[11];
    const float* b_ih_p   = (const float*)d_in[12];
    const float* b_hh_p   = (const float*)d_in[13];

    float* out      = (float*)d_out;
    float* outs     = out;                                   // (TN, H)
    float* hxs_out  = outs + (size_t)TN * H_DIM;             // (N, H)
    float* outs_p   = hxs_out + (size_t)NB * H_DIM;          // (TN, H)
    float* hys_out  = outs_p + (size_t)TN * H_DIM;           // (N, H)

    cudaFuncSetAttribute(scan_kernel, cudaFuncAttributeMaxDynamicSharedMemorySize,
                         SCAN_SMEM);

    // 1) prep
    ma_kernel<<<(TN * A_DIM + 255) / 256, 256>>>(pa, masks);
    split3_kernel<<<(G3 * K_IN / 8 + 255) / 256, 256>>>(w_ih, w_hh, w_hh_p);
    bar_reset_kernel<<<1, 1>>>();

    // 2) input GEMM: g_GI complete
    input_gemm_kernel<<<dim3(G3 / 48, TN / 256), 256>>>(x, b_ih);

    // 3) persistent scan: all 128 steps in one launch
    scan_kernel<<<128, 512, SCAN_SMEM>>>(hxs, hys, gru_init, masks,
                                         b_hh, b_hh_p, w_ih_p, b_ih_p,
                                         outs, outs_p);

    // 4) final hidden states = last timestep outputs
    cudaMemcpyAsync(hxs_out, outs   + (size_t)(T_STEPS - 1) * NB * H_DIM,
                    (size_t)NB * H_DIM * sizeof(float), cudaMemcpyDeviceToDevice);
    cudaMemcpyAsync(hys_out, outs_p + (size_t)(T_STEPS - 1) * NB * H_DIM,
                    (size_t)NB * H_DIM * sizeof(float), cudaMemcpyDeviceToDevice);
}